// round 10
// baseline (speedup 1.0000x reference)
#include <cuda_runtime.h>
#include <cuda_bf16.h>
#include <cstdint>

#define Bn 8
#define Tn 4096
#define Cn 384
#define Hn 6
#define Fn 64
#define En 131072
#define DFF 1536
#define BT (Bn * Tn)             // 32768
#define NEDGE (En + Tn)          // 135168
#define NEG_SLOPE 0.2f
#define LN_EPS 1e-5f

// ---------------- scratch (__device__ globals; no allocation) ----------------
__device__ __nv_bfloat16 g_xnb[BT * Cn];     // LN output (bf16), reused LN1/LN2
__device__ __nv_bfloat16 g_hb[BT * Cn];      // GAT projection h (bf16)
__device__ float         g_asrc[BT * Hn];
__device__ float         g_adst[BT * Hn];
__device__ float         g_y1[BT * Cn];      // x + gat_out (residual 1, fp32)
__device__ __nv_bfloat16 g_z[BT * DFF];      // FFN hidden (bf16)
__device__ __nv_bfloat16 g_w1t[DFF * Cn];    // W1^T  [DFF][C]
__device__ __nv_bfloat16 g_w2t[Cn * DFF];    // W2^T  [C][DFF]
__device__ __nv_bfloat16 g_wgt[Cn * Cn];     // W_gat^T
__device__ float         g_usrc[Hn * Cn];    // W_gat @ att_src per head
__device__ float         g_udst[Hn * Cn];
__device__ int g_cnt[Tn + 1];
__device__ int g_off[Tn + 1];
__device__ int g_cur[Tn];
__device__ int g_csrc[NEDGE];

// ---------------- PTX helpers ----------------
__device__ __forceinline__ uint32_t smem_u32(const void* p) {
    uint32_t a;
    asm("{ .reg .u64 t; cvta.to.shared.u64 t, %1; cvt.u32.u64 %0, t; }" : "=r"(a) : "l"(p));
    return a;
}
__device__ __forceinline__ void cp_async16(uint32_t dst, const void* src) {
    asm volatile("cp.async.cg.shared.global [%0], [%1], 16;" :: "r"(dst), "l"(src) : "memory");
}
__device__ __forceinline__ void cp_commit() {
    asm volatile("cp.async.commit_group;" ::: "memory");
}
__device__ __forceinline__ void cp_wait1() {
    asm volatile("cp.async.wait_group 1;" ::: "memory");
}
__device__ __forceinline__ void cp_wait0() {
    asm volatile("cp.async.wait_group 0;" ::: "memory");
}
__device__ __forceinline__ void ldmat_x4(uint32_t& r0, uint32_t& r1, uint32_t& r2, uint32_t& r3,
                                         uint32_t addr) {
    asm volatile("ldmatrix.sync.aligned.m8n8.x4.shared.b16 {%0,%1,%2,%3}, [%4];"
                 : "=r"(r0), "=r"(r1), "=r"(r2), "=r"(r3) : "r"(addr));
}
__device__ __forceinline__ void mma_bf16(float* d, const uint32_t* a, const uint32_t* b) {
    asm volatile(
        "mma.sync.aligned.m16n8k16.row.col.f32.bf16.bf16.f32 "
        "{%0,%1,%2,%3}, {%4,%5,%6,%7}, {%8,%9}, {%0,%1,%2,%3};"
        : "+f"(d[0]), "+f"(d[1]), "+f"(d[2]), "+f"(d[3])
        : "r"(a[0]), "r"(a[1]), "r"(a[2]), "r"(a[3]), "r"(b[0]), "r"(b[1]));
}

// SW64 swizzle for 64-byte smem rows (conflict-free for ldmatrix + cp.async)
__device__ __forceinline__ uint32_t sw64(uint32_t off) {
    return off ^ ((off >> 3) & 0x30);
}

// ---------------- bf16 HMMA GEMM: D[M,N] = A[M,K] @ Bt[N,K]^T ----------------
// MODE 0: fp32 plain; MODE 1: bf16 bias+relu; MODE 2: fp32 bias+residual; MODE 3: bf16 plain
// 128x128 CTA tile, BK=32, double-buffered cp.async, 8 warps (2M x 4N), warp tile 64x32.
// (Exact R5/497.8us-measured mainloop.)
template <int N, int K, int MODE>
__global__ __launch_bounds__(256, 2) void gemm_mma(
    const __nv_bfloat16* __restrict__ A,
    const __nv_bfloat16* __restrict__ Bt,
    const float* __restrict__ bias,
    const float* __restrict__ res,
    float* __restrict__ outf,
    __nv_bfloat16* __restrict__ outb)
{
    __shared__ __align__(1024) unsigned char smem[32768]; // [stage][A 8KB | B 8KB]
    const uint32_t sbase = smem_u32(smem);

    int tid = threadIdx.x;
    int wid = tid >> 5;
    int lane = tid & 31;
    int bm = blockIdx.y * 128;
    int bn = blockIdx.x * 128;
    int wm = (wid & 1) * 64;
    int wn = (wid >> 1) * 32;

    float acc[4][4][4];
#pragma unroll
    for (int i = 0; i < 4; i++)
#pragma unroll
        for (int j = 0; j < 4; j++)
#pragma unroll
            for (int d = 0; d < 4; d++) acc[i][j][d] = 0.f;

    const int KT = K / 32;

    auto load_stage = [&](int kt, int s) {
        int k0 = kt * 32;
        uint32_t sA = sbase + s * 16384;
        uint32_t sB = sA + 8192;
#pragma unroll
        for (int i = 0; i < 2; i++) {
            int idx = tid + i * 256;          // 0..511
            int r = idx >> 2, c = idx & 3;
            uint32_t sw = sw64(r * 64 + c * 16);
            cp_async16(sA + sw, A + (size_t)(bm + r) * K + k0 + c * 8);
            cp_async16(sB + sw, Bt + (size_t)(bn + r) * K + k0 + c * 8);
        }
    };

    load_stage(0, 0);
    cp_commit();

    for (int kt = 0; kt < KT; kt++) {
        if (kt + 1 < KT) {
            load_stage(kt + 1, (kt + 1) & 1);
            cp_commit();
            cp_wait1();
        } else {
            cp_wait0();
        }
        __syncthreads();

        uint32_t sA = sbase + (kt & 1) * 16384;
        uint32_t sB = sA + 8192;
#pragma unroll
        for (int ks = 0; ks < 2; ks++) {
            uint32_t af[4][4];
            uint32_t bf[4][2];
#pragma unroll
            for (int mi = 0; mi < 4; mi++) {
                int row = wm + mi * 16 + (lane & 15);
                int colb = (ks * 16 + ((lane >> 4) << 3)) * 2;
                ldmat_x4(af[mi][0], af[mi][1], af[mi][2], af[mi][3],
                         sA + sw64(row * 64 + colb));
            }
#pragma unroll
            for (int nj = 0; nj < 2; nj++) {
                int nrow = wn + nj * 16 + (lane & 7) + ((lane >> 4) << 3);
                int kcolb = (ks * 16 + (((lane >> 3) & 1) << 3)) * 2;
                uint32_t r0, r1, r2, r3;
                ldmat_x4(r0, r1, r2, r3, sB + sw64(nrow * 64 + kcolb));
                bf[nj * 2][0] = r0; bf[nj * 2][1] = r1;
                bf[nj * 2 + 1][0] = r2; bf[nj * 2 + 1][1] = r3;
            }
#pragma unroll
            for (int mi = 0; mi < 4; mi++)
#pragma unroll
                for (int ni = 0; ni < 4; ni++)
                    mma_bf16(acc[mi][ni], af[mi], bf[ni]);
        }
        __syncthreads();
    }

    int rq = lane >> 2;
    int cq = (lane & 3) * 2;
#pragma unroll
    for (int mi = 0; mi < 4; mi++) {
#pragma unroll
        for (int ni = 0; ni < 4; ni++) {
            int gm = bm + wm + mi * 16 + rq;
            int gn = bn + wn + ni * 8 + cq;
            float v0 = acc[mi][ni][0], v1 = acc[mi][ni][1];
            float v2 = acc[mi][ni][2], v3 = acc[mi][ni][3];
            if (MODE == 0) {
                *(float2*)(outf + (size_t)gm * N + gn) = make_float2(v0, v1);
                *(float2*)(outf + (size_t)(gm + 8) * N + gn) = make_float2(v2, v3);
            } else if (MODE == 1) {
                float b0 = bias[gn], b1 = bias[gn + 1];
                __nv_bfloat162 p0, p1;
                p0.x = __float2bfloat16(fmaxf(v0 + b0, 0.f));
                p0.y = __float2bfloat16(fmaxf(v1 + b1, 0.f));
                p1.x = __float2bfloat16(fmaxf(v2 + b0, 0.f));
                p1.y = __float2bfloat16(fmaxf(v3 + b1, 0.f));
                *(__nv_bfloat162*)(outb + (size_t)gm * N + gn) = p0;
                *(__nv_bfloat162*)(outb + (size_t)(gm + 8) * N + gn) = p1;
            } else if (MODE == 3) {
                __nv_bfloat162 p0, p1;
                p0.x = __float2bfloat16(v0); p0.y = __float2bfloat16(v1);
                p1.x = __float2bfloat16(v2); p1.y = __float2bfloat16(v3);
                *(__nv_bfloat162*)(outb + (size_t)gm * N + gn) = p0;
                *(__nv_bfloat162*)(outb + (size_t)(gm + 8) * N + gn) = p1;
            } else {
                float b0 = bias[gn], b1 = bias[gn + 1];
                float2 r0 = *(const float2*)(res + (size_t)gm * N + gn);
                float2 r1 = *(const float2*)(res + (size_t)(gm + 8) * N + gn);
                *(float2*)(outf + (size_t)gm * N + gn) = make_float2(v0 + b0 + r0.x, v1 + b1 + r0.y);
                *(float2*)(outf + (size_t)(gm + 8) * N + gn) = make_float2(v2 + b0 + r1.x, v3 + b1 + r1.y);
            }
        }
    }
}

// ---------------- weight transpose + fp32->bf16 ----------------
__global__ void transpose_bf16(const float* __restrict__ src, __nv_bfloat16* __restrict__ dst,
                               int Rs, int Cs) {
    __shared__ float t[32][33];
    int c = blockIdx.x * 32 + threadIdx.x;
    int r = blockIdx.y * 32 + threadIdx.y;
    t[threadIdx.y][threadIdx.x] = src[(size_t)r * Cs + c];
    __syncthreads();
    int oc = blockIdx.y * 32 + threadIdx.x;
    int orr = blockIdx.x * 32 + threadIdx.y;
    dst[(size_t)orr * Rs + oc] = __float2bfloat16(t[threadIdx.x][threadIdx.y]);
}

// ---------------- LayerNorm (fp32 in, bf16 out) ----------------
__global__ void ln_bf16_kernel(const float* __restrict__ x, const float* __restrict__ g,
                               const float* __restrict__ b, __nv_bfloat16* __restrict__ out) {
    int row = blockIdx.x;
    int tid = threadIdx.x; // 128
    const float* xr = x + (size_t)row * Cn;
    float v0 = xr[tid], v1 = xr[tid + 128], v2 = xr[tid + 256];
    float s  = v0 + v1 + v2;
    float s2 = v0 * v0 + v1 * v1 + v2 * v2;
#pragma unroll
    for (int o = 16; o; o >>= 1) {
        s  += __shfl_xor_sync(0xffffffffu, s,  o);
        s2 += __shfl_xor_sync(0xffffffffu, s2, o);
    }
    __shared__ float ps[4], ps2[4];
    if ((tid & 31) == 0) { ps[tid >> 5] = s; ps2[tid >> 5] = s2; }
    __syncthreads();
    s  = ps[0] + ps[1] + ps[2] + ps[3];
    s2 = ps2[0] + ps2[1] + ps2[2] + ps2[3];
    float mu  = s * (1.0f / Cn);
    float var = s2 * (1.0f / Cn) - mu * mu;
    float inv = rsqrtf(var + LN_EPS);
    __nv_bfloat16* orow = out + (size_t)row * Cn;
    orow[tid]       = __float2bfloat16((v0 - mu) * inv * g[tid]       + b[tid]);
    orow[tid + 128] = __float2bfloat16((v1 - mu) * inv * g[tid + 128] + b[tid + 128]);
    orow[tid + 256] = __float2bfloat16((v2 - mu) * inv * g[tid + 256] + b[tid + 256]);
}

// ---------------- u-vectors: u[h][c] = sum_f W_gat[c][h*64+f] * att[h][f] ----------------
__global__ void attn_u_kernel(const float* __restrict__ W_gat,
                              const float* __restrict__ att_src,
                              const float* __restrict__ att_dst) {
    int c = blockIdx.x * 128 + threadIdx.x;
    if (c >= Cn) return;
    const float* wr = W_gat + (size_t)c * Cn;
#pragma unroll
    for (int h = 0; h < Hn; h++) {
        float s1 = 0.f, s2 = 0.f;
#pragma unroll
        for (int f = 0; f < Fn; f++) {
            float wv = wr[h * Fn + f];
            s1 += wv * att_src[h * Fn + f];
            s2 += wv * att_dst[h * Fn + f];
        }
        g_usrc[h * Cn + c] = s1;
        g_udst[h * Cn + c] = s2;
    }
}

// ---------------- attention coefficients: warp per node, from xn (bf16) ----------------
__global__ void attn_coef_kernel(const __nv_bfloat16* __restrict__ Xn) {
    int n = blockIdx.x * 8 + (threadIdx.x >> 5);
    int lane = threadIdx.x & 31;
    if (n >= BT) return;
    int c0 = lane * 12;
    float xv[12];
    {
        const __nv_bfloat16* xr = Xn + (size_t)n * Cn + c0;
#pragma unroll
        for (int j = 0; j < 12; j += 2) {
            __nv_bfloat162 p = *(const __nv_bfloat162*)(xr + j);
            xv[j] = __bfloat162float(p.x);
            xv[j + 1] = __bfloat162float(p.y);
        }
    }
#pragma unroll
    for (int h = 0; h < Hn; h++) {
        float s1 = 0.f, s2 = 0.f;
        const float* u1 = g_usrc + h * Cn + c0;
        const float* u2 = g_udst + h * Cn + c0;
#pragma unroll
        for (int j = 0; j < 12; j++) {
            s1 += xv[j] * u1[j];
            s2 += xv[j] * u2[j];
        }
#pragma unroll
        for (int o = 16; o; o >>= 1) {
            s1 += __shfl_xor_sync(0xffffffffu, s1, o);
            s2 += __shfl_xor_sync(0xffffffffu, s2, o);
        }
        if (lane == 0) {
            g_asrc[(size_t)n * Hn + h] = s1;
            g_adst[(size_t)n * Hn + h] = s2;
        }
    }
}

// ---------------- CSR build ----------------
__global__ void zero_cnt_kernel() {
    int i = blockIdx.x * blockDim.x + threadIdx.x;
    if (i <= Tn) g_cnt[i] = 0;
}
__global__ void hist_kernel(const int* __restrict__ edge_dst) {
    int e = blockIdx.x * blockDim.x + threadIdx.x;
    if (e >= NEDGE) return;
    int d = (e < En) ? edge_dst[e] : (e - En);
    atomicAdd(&g_cnt[d], 1);
}
__global__ void scan_kernel() {
    __shared__ int sm[1024];
    int t = threadIdx.x;
    int c0 = g_cnt[4 * t + 0], c1 = g_cnt[4 * t + 1];
    int c2 = g_cnt[4 * t + 2], c3 = g_cnt[4 * t + 3];
    int val = c0 + c1 + c2 + c3;
    sm[t] = val;
    __syncthreads();
    for (int d = 1; d < 1024; d <<= 1) {
        int v = (t >= d) ? sm[t - d] : 0;
        __syncthreads();
        if (t >= d) sm[t] += v;
        __syncthreads();
    }
    int base = sm[t] - val;
    g_off[4 * t + 0] = base;                g_cur[4 * t + 0] = base;
    g_off[4 * t + 1] = base + c0;           g_cur[4 * t + 1] = base + c0;
    g_off[4 * t + 2] = base + c0 + c1;      g_cur[4 * t + 2] = base + c0 + c1;
    g_off[4 * t + 3] = base + c0 + c1 + c2; g_cur[4 * t + 3] = base + c0 + c1 + c2;
    if (t == 1023) g_off[Tn] = sm[1023];
}
__global__ void scatter_kernel(const int* __restrict__ edge_src,
                               const int* __restrict__ edge_dst) {
    int e = blockIdx.x * blockDim.x + threadIdx.x;
    if (e >= NEDGE) return;
    int s, d;
    if (e < En) { s = edge_src[e]; d = edge_dst[e]; }
    else        { s = e - En;      d = e - En; }
    int p = atomicAdd(&g_cur[d], 1);
    g_csrc[p] = s;
}

// ---------------- GAT aggregation v2 (R5-measured): warp per (b,t,h), 2 edges/iter ----------------
__global__ void gat_agg_kernel(const __nv_bfloat16* __restrict__ Hb,
                               const float* __restrict__ asrc,
                               const float* __restrict__ adst,
                               const float* __restrict__ x,
                               const float* __restrict__ bgat,
                               float* __restrict__ y1) {
    int w = blockIdx.x * 8 + (threadIdx.x >> 5);
    int lane = threadIdx.x & 31;
    if (w >= Bn * Tn * Hn) return;
    int h = w % Hn;
    int n = w / Hn;      // b*T + t
    int t = n % Tn;
    int b = n / Tn;
    int half = lane >> 4;     // 0/1
    int sub = lane & 15;      // feature group: 4 bf16 each
    int beg = g_off[t], end = g_off[t + 1];
    int nb = b * Tn;
    float a_d = adst[(size_t)n * Hn + h];

    float den = 0.f;
    float acc0 = 0.f, acc1 = 0.f, acc2 = 0.f, acc3 = 0.f;

    for (int e = beg + half; e < end; e += 2) {
        int s = g_csrc[e];
        int row = nb + s;
        float al = asrc[(size_t)row * Hn + h] + a_d;
        al = (al >= 0.f) ? al : NEG_SLOPE * al;
        float wgt = __expf(al);
        den += wgt;
        uint2 raw = *(const uint2*)(Hb + (size_t)row * Cn + h * Fn + sub * 4);
        __nv_bfloat162 p0 = *(__nv_bfloat162*)&raw.x;
        __nv_bfloat162 p1 = *(__nv_bfloat162*)&raw.y;
        acc0 += wgt * __bfloat162float(p0.x);
        acc1 += wgt * __bfloat162float(p0.y);
        acc2 += wgt * __bfloat162float(p1.x);
        acc3 += wgt * __bfloat162float(p1.y);
    }
    den  += __shfl_xor_sync(0xffffffffu, den,  16);
    acc0 += __shfl_xor_sync(0xffffffffu, acc0, 16);
    acc1 += __shfl_xor_sync(0xffffffffu, acc1, 16);
    acc2 += __shfl_xor_sync(0xffffffffu, acc2, 16);
    acc3 += __shfl_xor_sync(0xffffffffu, acc3, 16);

    if (half == 0) {
        float inv = 1.f / den;
        int c = h * Fn + sub * 4;
        size_t o = (size_t)n * Cn + c;
        float4 xo = *(const float4*)(x + o);
        float4 bg = *(const float4*)(bgat + c);
        float4 r;
        r.x = xo.x + acc0 * inv + bg.x;
        r.y = xo.y + acc1 * inv + bg.y;
        r.z = xo.z + acc2 * inv + bg.z;
        r.w = xo.w + acc3 * inv + bg.w;
        *(float4*)(y1 + o) = r;
    }
}

// ---------------- launch ----------------
extern "C" void kernel_launch(void* const* d_in, const int* in_sizes, int n_in,
                              void* d_out, int out_size) {
    const float* x        = (const float*)d_in[0];
    const int*   edge     = (const int*)d_in[1];
    const float* W_gat    = (const float*)d_in[2];
    const float* att_src  = (const float*)d_in[3];
    const float* att_dst  = (const float*)d_in[4];
    const float* b_gat    = (const float*)d_in[5];
    const float* ln1_g    = (const float*)d_in[6];
    const float* ln1_b    = (const float*)d_in[7];
    const float* ln2_g    = (const float*)d_in[8];
    const float* ln2_b    = (const float*)d_in[9];
    const float* W1       = (const float*)d_in[10];
    const float* b1       = (const float*)d_in[11];
    const float* W2       = (const float*)d_in[12];
    const float* b2       = (const float*)d_in[13];
    float* out = (float*)d_out;

    const int* edge_src = edge;
    const int* edge_dst = edge + En;

    __nv_bfloat16 *xnb, *hb, *z, *w1t, *w2t, *wgt;
    float *asrc, *adst, *y1;
    cudaGetSymbolAddress((void**)&xnb,  g_xnb);
    cudaGetSymbolAddress((void**)&hb,   g_hb);
    cudaGetSymbolAddress((void**)&asrc, g_asrc);
    cudaGetSymbolAddress((void**)&adst, g_adst);
    cudaGetSymbolAddress((void**)&y1,   g_y1);
    cudaGetSymbolAddress((void**)&z,    g_z);
    cudaGetSymbolAddress((void**)&w1t,  g_w1t);
    cudaGetSymbolAddress((void**)&w2t,  g_w2t);
    cudaGetSymbolAddress((void**)&wgt,  g_wgt);

    // (1) zero counters, (2) LN1, (3) W_gat^T, (4) GAT GEMM  <- profiled slot
    zero_cnt_kernel<<<(Tn + 256) / 256, 256>>>();
    ln_bf16_kernel<<<BT, 128>>>(x, ln1_g, ln1_b, xnb);
    transpose_bf16<<<dim3(Cn / 32, Cn / 32), dim3(32, 32)>>>(W_gat, wgt, Cn, Cn);
    gemm_mma<Cn, Cn, 3><<<dim3(Cn / 128, BT / 128), 256>>>(
        xnb, wgt, nullptr, nullptr, nullptr, hb);

    // CSR build (graph shared across batch)
    hist_kernel<<<(NEDGE + 255) / 256, 256>>>(edge_dst);
    scan_kernel<<<1, 1024>>>();
    scatter_kernel<<<(NEDGE + 255) / 256, 256>>>(edge_src, edge_dst);

    // remaining weight transposes
    transpose_bf16<<<dim3(DFF / 32, Cn / 32), dim3(32, 32)>>>(W1, w1t, Cn, DFF);
    transpose_bf16<<<dim3(Cn / 32, DFF / 32), dim3(32, 32)>>>(W2, w2t, DFF, Cn);

    // attention coefficients from xn and u-vectors
    attn_u_kernel<<<(Cn + 127) / 128, 128>>>(W_gat, att_src, att_dst);
    attn_coef_kernel<<<(BT + 7) / 8, 256>>>(xnb);

    // segment softmax + aggregation + residual
    gat_agg_kernel<<<(Bn * Tn * Hn) / 8, 256>>>(hb, asrc, adst, x, b_gat, y1);
    // LN2 -> bf16
    ln_bf16_kernel<<<BT, 128>>>(y1, ln2_g, ln2_b, xnb);
    // FFN1: Z = relu(xn @ W1 + b1)  (bf16 out)
    gemm_mma<DFF, Cn, 1><<<dim3(DFF / 128, BT / 128), 256>>>(
        xnb, w1t, b1, nullptr, nullptr, z);
    // FFN2: out = Z @ W2 + b2 + y1 (fp32 out)
    gemm_mma<Cn, DFF, 2><<<dim3(Cn / 128, BT / 128), 256>>>(
        z, w2t, b2, y1, out, nullptr);
}

// round 12
// speedup vs baseline: 1.6285x; 1.6285x over previous
#include <cuda_runtime.h>
#include <cuda_bf16.h>
#include <cstdint>

#define Bn 8
#define Tn 4096
#define Cn 384
#define Hn 6
#define Fn 64
#define En 131072
#define DFF 1536
#define BT (Bn * Tn)             // 32768
#define NEDGE (En + Tn)          // 135168
#define NEG_SLOPE 0.2f
#define LN_EPS 1e-5f

// ---------------- scratch (__device__ globals; no allocation) ----------------
__device__ __nv_bfloat16 g_xnb[BT * Cn];     // LN output (bf16), reused LN1/LN2
__device__ __nv_bfloat16 g_hb[BT * Cn];      // GAT projection h (bf16)
__device__ float         g_asrc[BT * Hn];
__device__ float         g_adst[BT * Hn];
__device__ float         g_y1[BT * Cn];      // x + gat_out (residual 1, fp32)
__device__ __nv_bfloat16 g_z[BT * DFF];      // FFN hidden (bf16)
__device__ __nv_bfloat16 g_w1t[DFF * Cn];    // W1^T  [DFF][C]
__device__ __nv_bfloat16 g_w2t[Cn * DFF];    // W2^T  [C][DFF]
__device__ __nv_bfloat16 g_wgt[Cn * Cn];     // W_gat^T
__device__ float         g_usrc[Hn * Cn];    // W_gat @ att_src per head
__device__ float         g_udst[Hn * Cn];
__device__ int g_cnt[Tn + 1];
__device__ int g_off[Tn + 1];
__device__ int g_cur[Tn];
__device__ int g_csrc[NEDGE];

// ---------------- PTX helpers ----------------
__device__ __forceinline__ uint32_t smem_u32(const void* p) {
    uint32_t a;
    asm("{ .reg .u64 t; cvta.to.shared.u64 t, %1; cvt.u32.u64 %0, t; }" : "=r"(a) : "l"(p));
    return a;
}
__device__ __forceinline__ void cp_async16(uint32_t dst, const void* src) {
    asm volatile("cp.async.cg.shared.global [%0], [%1], 16;" :: "r"(dst), "l"(src) : "memory");
}
__device__ __forceinline__ void cp_commit() {
    asm volatile("cp.async.commit_group;" ::: "memory");
}
__device__ __forceinline__ void cp_wait1() {
    asm volatile("cp.async.wait_group 1;" ::: "memory");
}
__device__ __forceinline__ void cp_wait0() {
    asm volatile("cp.async.wait_group 0;" ::: "memory");
}
__device__ __forceinline__ void ldmat_x4(uint32_t& r0, uint32_t& r1, uint32_t& r2, uint32_t& r3,
                                         uint32_t addr) {
    asm volatile("ldmatrix.sync.aligned.m8n8.x4.shared.b16 {%0,%1,%2,%3}, [%4];"
                 : "=r"(r0), "=r"(r1), "=r"(r2), "=r"(r3) : "r"(addr));
}
__device__ __forceinline__ void mma_bf16(float* d, const uint32_t* a, const uint32_t* b) {
    asm volatile(
        "mma.sync.aligned.m16n8k16.row.col.f32.bf16.bf16.f32 "
        "{%0,%1,%2,%3}, {%4,%5,%6,%7}, {%8,%9}, {%0,%1,%2,%3};"
        : "+f"(d[0]), "+f"(d[1]), "+f"(d[2]), "+f"(d[3])
        : "r"(a[0]), "r"(a[1]), "r"(a[2]), "r"(a[3]), "r"(b[0]), "r"(b[1]));
}

// SW64 swizzle for 64-byte smem rows (conflict-free for ldmatrix + cp.async)
__device__ __forceinline__ uint32_t sw64(uint32_t off) {
    return off ^ ((off >> 3) & 0x30);
}

// ---------------- bf16 HMMA GEMM: D[M,N] = A[M,K] @ Bt[N,K]^T ----------------
// MODE 0: fp32 plain; MODE 1: bf16 bias+relu; MODE 2: fp32 bias+residual; MODE 3: bf16 plain
// 128x128 CTA tile, BK=32, 3-stage cp.async, ONE sync per k-iter:
//   wait(group kt) -> sync -> prefetch(kt+2) -> compute(kt)
// The single sync both publishes stage kt and licenses overwrite of stage (kt+2)%3
// (all warps past compute kt-1; within a sync window warps touch stages kt%3 and
// (kt+1)%3 for compute, (kt+2)%3 for the prefetch write - all distinct).
template <int N, int K, int MODE>
__global__ __launch_bounds__(256, 2) void gemm_mma(
    const __nv_bfloat16* __restrict__ A,
    const __nv_bfloat16* __restrict__ Bt,
    const float* __restrict__ bias,
    const float* __restrict__ res,
    float* __restrict__ outf,
    __nv_bfloat16* __restrict__ outb)
{
    __shared__ __align__(1024) unsigned char smem[49152]; // 3 stages x (A 8KB | B 8KB)
    const uint32_t sbase = smem_u32(smem);

    int tid = threadIdx.x;
    int wid = tid >> 5;
    int lane = tid & 31;
    int bm = blockIdx.y * 128;
    int bn = blockIdx.x * 128;
    int wm = (wid & 1) * 64;
    int wn = (wid >> 1) * 32;

    float acc[4][4][4];
#pragma unroll
    for (int i = 0; i < 4; i++)
#pragma unroll
        for (int j = 0; j < 4; j++)
#pragma unroll
            for (int d = 0; d < 4; d++) acc[i][j][d] = 0.f;

    const int KT = K / 32;

    auto load_stage = [&](int kt, int s) {
        int k0 = kt * 32;
        uint32_t sA = sbase + s * 16384;
        uint32_t sB = sA + 8192;
#pragma unroll
        for (int i = 0; i < 2; i++) {
            int idx = tid + i * 256;          // 0..511
            int r = idx >> 2, c = idx & 3;
            uint32_t sw = sw64(r * 64 + c * 16);
            cp_async16(sA + sw, A + (size_t)(bm + r) * K + k0 + c * 8);
            cp_async16(sB + sw, Bt + (size_t)(bn + r) * K + k0 + c * 8);
        }
    };

    load_stage(0, 0);
    cp_commit();
    if (KT > 1) { load_stage(1, 1); cp_commit(); }

    for (int kt = 0; kt < KT; kt++) {
        if (kt + 1 < KT) cp_wait1(); else cp_wait0();
        __syncthreads();
        if (kt + 2 < KT) { load_stage(kt + 2, (kt + 2) % 3); cp_commit(); }

        uint32_t sA = sbase + (kt % 3) * 16384;
        uint32_t sB = sA + 8192;
#pragma unroll
        for (int ks = 0; ks < 2; ks++) {
            uint32_t af[4][4];
            uint32_t bf[4][2];
#pragma unroll
            for (int mi = 0; mi < 4; mi++) {
                int row = wm + mi * 16 + (lane & 15);
                int colb = (ks * 16 + ((lane >> 4) << 3)) * 2;
                ldmat_x4(af[mi][0], af[mi][1], af[mi][2], af[mi][3],
                         sA + sw64(row * 64 + colb));
            }
#pragma unroll
            for (int nj = 0; nj < 2; nj++) {
                int nrow = wn + nj * 16 + (lane & 7) + ((lane >> 4) << 3);
                int kcolb = (ks * 16 + (((lane >> 3) & 1) << 3)) * 2;
                uint32_t r0, r1, r2, r3;
                ldmat_x4(r0, r1, r2, r3, sB + sw64(nrow * 64 + kcolb));
                bf[nj * 2][0] = r0; bf[nj * 2][1] = r1;
                bf[nj * 2 + 1][0] = r2; bf[nj * 2 + 1][1] = r3;
            }
#pragma unroll
            for (int mi = 0; mi < 4; mi++)
#pragma unroll
                for (int ni = 0; ni < 4; ni++)
                    mma_bf16(acc[mi][ni], af[mi], bf[ni]);
        }
    }

    int rq = lane >> 2;
    int cq = (lane & 3) * 2;
#pragma unroll
    for (int mi = 0; mi < 4; mi++) {
#pragma unroll
        for (int ni = 0; ni < 4; ni++) {
            int gm = bm + wm + mi * 16 + rq;
            int gn = bn + wn + ni * 8 + cq;
            float v0 = acc[mi][ni][0], v1 = acc[mi][ni][1];
            float v2 = acc[mi][ni][2], v3 = acc[mi][ni][3];
            if (MODE == 0) {
                *(float2*)(outf + (size_t)gm * N + gn) = make_float2(v0, v1);
                *(float2*)(outf + (size_t)(gm + 8) * N + gn) = make_float2(v2, v3);
            } else if (MODE == 1) {
                float b0 = bias[gn], b1 = bias[gn + 1];
                __nv_bfloat162 p0, p1;
                p0.x = __float2bfloat16(fmaxf(v0 + b0, 0.f));
                p0.y = __float2bfloat16(fmaxf(v1 + b1, 0.f));
                p1.x = __float2bfloat16(fmaxf(v2 + b0, 0.f));
                p1.y = __float2bfloat16(fmaxf(v3 + b1, 0.f));
                *(__nv_bfloat162*)(outb + (size_t)gm * N + gn) = p0;
                *(__nv_bfloat162*)(outb + (size_t)(gm + 8) * N + gn) = p1;
            } else if (MODE == 3) {
                __nv_bfloat162 p0, p1;
                p0.x = __float2bfloat16(v0); p0.y = __float2bfloat16(v1);
                p1.x = __float2bfloat16(v2); p1.y = __float2bfloat16(v3);
                *(__nv_bfloat162*)(outb + (size_t)gm * N + gn) = p0;
                *(__nv_bfloat162*)(outb + (size_t)(gm + 8) * N + gn) = p1;
            } else {
                float b0 = bias[gn], b1 = bias[gn + 1];
                float2 r0 = *(const float2*)(res + (size_t)gm * N + gn);
                float2 r1 = *(const float2*)(res + (size_t)(gm + 8) * N + gn);
                *(float2*)(outf + (size_t)gm * N + gn) = make_float2(v0 + b0 + r0.x, v1 + b1 + r0.y);
                *(float2*)(outf + (size_t)(gm + 8) * N + gn) = make_float2(v2 + b0 + r1.x, v3 + b1 + r1.y);
            }
        }
    }
}

// ---------------- weight transpose + fp32->bf16 ----------------
__global__ void transpose_bf16(const float* __restrict__ src, __nv_bfloat16* __restrict__ dst,
                               int Rs, int Cs) {
    __shared__ float t[32][33];
    int c = blockIdx.x * 32 + threadIdx.x;
    int r = blockIdx.y * 32 + threadIdx.y;
    t[threadIdx.y][threadIdx.x] = src[(size_t)r * Cs + c];
    __syncthreads();
    int oc = blockIdx.y * 32 + threadIdx.x;
    int orr = blockIdx.x * 32 + threadIdx.y;
    dst[(size_t)orr * Rs + oc] = __float2bfloat16(t[threadIdx.x][threadIdx.y]);
}

// ---------------- LayerNorm (fp32 in, bf16 out) ----------------
__global__ void ln_bf16_kernel(const float* __restrict__ x, const float* __restrict__ g,
                               const float* __restrict__ b, __nv_bfloat16* __restrict__ out) {
    int row = blockIdx.x;
    int tid = threadIdx.x; // 128
    const float* xr = x + (size_t)row * Cn;
    float v0 = xr[tid], v1 = xr[tid + 128], v2 = xr[tid + 256];
    float s  = v0 + v1 + v2;
    float s2 = v0 * v0 + v1 * v1 + v2 * v2;
#pragma unroll
    for (int o = 16; o; o >>= 1) {
        s  += __shfl_xor_sync(0xffffffffu, s,  o);
        s2 += __shfl_xor_sync(0xffffffffu, s2, o);
    }
    __shared__ float ps[4], ps2[4];
    if ((tid & 31) == 0) { ps[tid >> 5] = s; ps2[tid >> 5] = s2; }
    __syncthreads();
    s  = ps[0] + ps[1] + ps[2] + ps[3];
    s2 = ps2[0] + ps2[1] + ps2[2] + ps2[3];
    float mu  = s * (1.0f / Cn);
    float var = s2 * (1.0f / Cn) - mu * mu;
    float inv = rsqrtf(var + LN_EPS);
    __nv_bfloat16* orow = out + (size_t)row * Cn;
    orow[tid]       = __float2bfloat16((v0 - mu) * inv * g[tid]       + b[tid]);
    orow[tid + 128] = __float2bfloat16((v1 - mu) * inv * g[tid + 128] + b[tid + 128]);
    orow[tid + 256] = __float2bfloat16((v2 - mu) * inv * g[tid + 256] + b[tid + 256]);
}

// ---------------- u-vectors: u[h][c] = sum_f W_gat[c][h*64+f] * att[h][f] ----------------
__global__ void attn_u_kernel(const float* __restrict__ W_gat,
                              const float* __restrict__ att_src,
                              const float* __restrict__ att_dst) {
    int c = blockIdx.x * 128 + threadIdx.x;
    if (c >= Cn) return;
    const float* wr = W_gat + (size_t)c * Cn;
#pragma unroll
    for (int h = 0; h < Hn; h++) {
        float s1 = 0.f, s2 = 0.f;
#pragma unroll
        for (int f = 0; f < Fn; f++) {
            float wv = wr[h * Fn + f];
            s1 += wv * att_src[h * Fn + f];
            s2 += wv * att_dst[h * Fn + f];
        }
        g_usrc[h * Cn + c] = s1;
        g_udst[h * Cn + c] = s2;
    }
}

// ---------------- attention coefficients: warp per node, from xn (bf16) ----------------
__global__ void attn_coef_kernel(const __nv_bfloat16* __restrict__ Xn) {
    int n = blockIdx.x * 8 + (threadIdx.x >> 5);
    int lane = threadIdx.x & 31;
    if (n >= BT) return;
    int c0 = lane * 12;
    float xv[12];
    {
        const __nv_bfloat16* xr = Xn + (size_t)n * Cn + c0;
#pragma unroll
        for (int j = 0; j < 12; j += 2) {
            __nv_bfloat162 p = *(const __nv_bfloat162*)(xr + j);
            xv[j] = __bfloat162float(p.x);
            xv[j + 1] = __bfloat162float(p.y);
        }
    }
#pragma unroll
    for (int h = 0; h < Hn; h++) {
        float s1 = 0.f, s2 = 0.f;
        const float* u1 = g_usrc + h * Cn + c0;
        const float* u2 = g_udst + h * Cn + c0;
#pragma unroll
        for (int j = 0; j < 12; j++) {
            s1 += xv[j] * u1[j];
            s2 += xv[j] * u2[j];
        }
#pragma unroll
        for (int o = 16; o; o >>= 1) {
            s1 += __shfl_xor_sync(0xffffffffu, s1, o);
            s2 += __shfl_xor_sync(0xffffffffu, s2, o);
        }
        if (lane == 0) {
            g_asrc[(size_t)n * Hn + h] = s1;
            g_adst[(size_t)n * Hn + h] = s2;
        }
    }
}

// ---------------- CSR build ----------------
__global__ void zero_cnt_kernel() {
    int i = blockIdx.x * blockDim.x + threadIdx.x;
    if (i <= Tn) g_cnt[i] = 0;
}
__global__ void hist_kernel(const int* __restrict__ edge_dst) {
    int e = blockIdx.x * blockDim.x + threadIdx.x;
    if (e >= NEDGE) return;
    int d = (e < En) ? edge_dst[e] : (e - En);
    atomicAdd(&g_cnt[d], 1);
}
__global__ void scan_kernel() {
    __shared__ int sm[1024];
    int t = threadIdx.x;
    int c0 = g_cnt[4 * t + 0], c1 = g_cnt[4 * t + 1];
    int c2 = g_cnt[4 * t + 2], c3 = g_cnt[4 * t + 3];
    int val = c0 + c1 + c2 + c3;
    sm[t] = val;
    __syncthreads();
    for (int d = 1; d < 1024; d <<= 1) {
        int v = (t >= d) ? sm[t - d] : 0;
        __syncthreads();
        if (t >= d) sm[t] += v;
        __syncthreads();
    }
    int base = sm[t] - val;
    g_off[4 * t + 0] = base;                g_cur[4 * t + 0] = base;
    g_off[4 * t + 1] = base + c0;           g_cur[4 * t + 1] = base + c0;
    g_off[4 * t + 2] = base + c0 + c1;      g_cur[4 * t + 2] = base + c0 + c1;
    g_off[4 * t + 3] = base + c0 + c1 + c2; g_cur[4 * t + 3] = base + c0 + c1 + c2;
    if (t == 1023) g_off[Tn] = sm[1023];
}
__global__ void scatter_kernel(const int* __restrict__ edge_src,
                               const int* __restrict__ edge_dst) {
    int e = blockIdx.x * blockDim.x + threadIdx.x;
    if (e >= NEDGE) return;
    int s, d;
    if (e < En) { s = edge_src[e]; d = edge_dst[e]; }
    else        { s = e - En;      d = e - En; }
    int p = atomicAdd(&g_cur[d], 1);
    g_csrc[p] = s;
}

// ---------------- GAT aggregation v3: warp per (b,t,h), 4 edges/iter ----------------
__global__ void gat_agg_kernel(const __nv_bfloat16* __restrict__ Hb,
                               const float* __restrict__ asrc,
                               const float* __restrict__ adst,
                               const float* __restrict__ x,
                               const float* __restrict__ bgat,
                               float* __restrict__ y1) {
    int w = blockIdx.x * 8 + (threadIdx.x >> 5);
    int lane = threadIdx.x & 31;
    if (w >= Bn * Tn * Hn) return;
    int h = w % Hn;
    int n = w / Hn;      // b*T + t
    int t = n % Tn;
    int b = n / Tn;
    int quarter = lane >> 3;   // 0..3
    int sub = lane & 7;        // feature group: 8 bf16 = 16B
    int beg = g_off[t], end = g_off[t + 1];
    int nb = b * Tn;
    float a_d = adst[(size_t)n * Hn + h];

    float den = 0.f;
    float acc[8] = {};

    for (int e = beg + quarter; e < end; e += 4) {
        int s = g_csrc[e];
        int row = nb + s;
        float al = asrc[(size_t)row * Hn + h] + a_d;
        al = (al >= 0.f) ? al : NEG_SLOPE * al;
        float wgt = __expf(al);
        den += wgt;
        uint4 raw = *(const uint4*)(Hb + (size_t)row * Cn + h * Fn + sub * 8);
        __nv_bfloat162 p0 = *(__nv_bfloat162*)&raw.x;
        __nv_bfloat162 p1 = *(__nv_bfloat162*)&raw.y;
        __nv_bfloat162 p2 = *(__nv_bfloat162*)&raw.z;
        __nv_bfloat162 p3 = *(__nv_bfloat162*)&raw.w;
        acc[0] += wgt * __bfloat162float(p0.x);
        acc[1] += wgt * __bfloat162float(p0.y);
        acc[2] += wgt * __bfloat162float(p1.x);
        acc[3] += wgt * __bfloat162float(p1.y);
        acc[4] += wgt * __bfloat162float(p2.x);
        acc[5] += wgt * __bfloat162float(p2.y);
        acc[6] += wgt * __bfloat162float(p3.x);
        acc[7] += wgt * __bfloat162float(p3.y);
    }
#pragma unroll
    for (int o = 8; o <= 16; o <<= 1) {
        den += __shfl_xor_sync(0xffffffffu, den, o);
#pragma unroll
        for (int j = 0; j < 8; j++)
            acc[j] += __shfl_xor_sync(0xffffffffu, acc[j], o);
    }

    if (quarter == 0) {
        float inv = 1.f / den;
        int c = h * Fn + sub * 8;
        size_t o = (size_t)n * Cn + c;
        float4 x0 = *(const float4*)(x + o);
        float4 x1 = *(const float4*)(x + o + 4);
        float4 bg0 = *(const float4*)(bgat + c);
        float4 bg1 = *(const float4*)(bgat + c + 4);
        float4 r0, r1;
        r0.x = x0.x + acc[0] * inv + bg0.x;
        r0.y = x0.y + acc[1] * inv + bg0.y;
        r0.z = x0.z + acc[2] * inv + bg0.z;
        r0.w = x0.w + acc[3] * inv + bg0.w;
        r1.x = x1.x + acc[4] * inv + bg1.x;
        r1.y = x1.y + acc[5] * inv + bg1.y;
        r1.z = x1.z + acc[6] * inv + bg1.z;
        r1.w = x1.w + acc[7] * inv + bg1.w;
        *(float4*)(y1 + o) = r0;
        *(float4*)(y1 + o + 4) = r1;
    }
}

// ---------------- launch ----------------
extern "C" void kernel_launch(void* const* d_in, const int* in_sizes, int n_in,
                              void* d_out, int out_size) {
    const float* x        = (const float*)d_in[0];
    const int*   edge     = (const int*)d_in[1];
    const float* W_gat    = (const float*)d_in[2];
    const float* att_src  = (const float*)d_in[3];
    const float* att_dst  = (const float*)d_in[4];
    const float* b_gat    = (const float*)d_in[5];
    const float* ln1_g    = (const float*)d_in[6];
    const float* ln1_b    = (const float*)d_in[7];
    const float* ln2_g    = (const float*)d_in[8];
    const float* ln2_b    = (const float*)d_in[9];
    const float* W1       = (const float*)d_in[10];
    const float* b1       = (const float*)d_in[11];
    const float* W2       = (const float*)d_in[12];
    const float* b2       = (const float*)d_in[13];
    float* out = (float*)d_out;

    const int* edge_src = edge;
    const int* edge_dst = edge + En;

    __nv_bfloat16 *xnb, *hb, *z, *w1t, *w2t, *wgt;
    float *asrc, *adst, *y1;
    cudaGetSymbolAddress((void**)&xnb,  g_xnb);
    cudaGetSymbolAddress((void**)&hb,   g_hb);
    cudaGetSymbolAddress((void**)&asrc, g_asrc);
    cudaGetSymbolAddress((void**)&adst, g_adst);
    cudaGetSymbolAddress((void**)&y1,   g_y1);
    cudaGetSymbolAddress((void**)&z,    g_z);
    cudaGetSymbolAddress((void**)&w1t,  g_w1t);
    cudaGetSymbolAddress((void**)&w2t,  g_w2t);
    cudaGetSymbolAddress((void**)&wgt,  g_wgt);

    // (1) zero counters, (2) LN1, (3) W_gat^T, (4) GAT GEMM  <- profiled slot
    zero_cnt_kernel<<<(Tn + 256) / 256, 256>>>();
    ln_bf16_kernel<<<BT, 128>>>(x, ln1_g, ln1_b, xnb);
    transpose_bf16<<<dim3(Cn / 32, Cn / 32), dim3(32, 32)>>>(W_gat, wgt, Cn, Cn);
    gemm_mma<Cn, Cn, 3><<<dim3(Cn / 128, BT / 128), 256>>>(
        xnb, wgt, nullptr, nullptr, nullptr, hb);

    // CSR build (graph shared across batch)
    hist_kernel<<<(NEDGE + 255) / 256, 256>>>(edge_dst);
    scan_kernel<<<1, 1024>>>();
    scatter_kernel<<<(NEDGE + 255) / 256, 256>>>(edge_src, edge_dst);

    // remaining weight transposes
    transpose_bf16<<<dim3(DFF / 32, Cn / 32), dim3(32, 32)>>>(W1, w1t, Cn, DFF);
    transpose_bf16<<<dim3(Cn / 32, DFF / 32), dim3(32, 32)>>>(W2, w2t, DFF, Cn);

    // attention coefficients from xn and u-vectors
    attn_u_kernel<<<(Cn + 127) / 128, 128>>>(W_gat, att_src, att_dst);
    attn_coef_kernel<<<(BT + 7) / 8, 256>>>(xnb);

    // segment softmax + aggregation + residual
    gat_agg_kernel<<<(Bn * Tn * Hn) / 8, 256>>>(hb, asrc, adst, x, b_gat, y1);
    // LN2 -> bf16
    ln_bf16_kernel<<<BT, 128>>>(y1, ln2_g, ln2_b, xnb);
    // FFN1: Z = relu(xn @ W1 + b1)  (bf16 out)
    gemm_mma<DFF, Cn, 1><<<dim3(DFF / 128, BT / 128), 256>>>(
        xnb, w1t, b1, nullptr, nullptr, z);
    // FFN2: out = Z @ W2 + b2 + y1 (fp32 out)
    gemm_mma<Cn, DFF, 2><<<dim3(Cn / 128, BT / 128), 256>>>(
        z, w2t, b2, y1, out, nullptr);
}

// round 14
// speedup vs baseline: 1.6831x; 1.0335x over previous
#include <cuda_runtime.h>
#include <cuda_bf16.h>
#include <cstdint>

#define Bn 8
#define Tn 4096
#define Cn 384
#define Hn 6
#define Fn 64
#define En 131072
#define DFF 1536
#define BT (Bn * Tn)             // 32768
#define NEDGE (En + Tn)          // 135168
#define NEG_SLOPE 0.2f
#define LN_EPS 1e-5f

// ---------------- scratch (__device__ globals; no allocation) ----------------
__device__ __nv_bfloat16 g_xnb[BT * Cn];     // LN output (bf16), reused LN1/LN2
__device__ __nv_bfloat16 g_hb[BT * Cn];      // GAT projection h (bf16)
__device__ float         g_asrc[BT * Hn];
__device__ float         g_adst[BT * Hn];
__device__ float         g_y1[BT * Cn];      // x + gat_out (residual 1, fp32)
__device__ __nv_bfloat16 g_z[BT * DFF];      // FFN hidden (bf16)
__device__ __nv_bfloat16 g_w1t[DFF * Cn];    // W1^T  [DFF][C]
__device__ __nv_bfloat16 g_w2t[Cn * DFF];    // W2^T  [C][DFF]
__device__ __nv_bfloat16 g_wgt[Cn * Cn];     // W_gat^T
__device__ float         g_usrc[Hn * Cn];    // W_gat @ att_src per head
__device__ float         g_udst[Hn * Cn];
__device__ int g_cnt[Tn + 1];
__device__ int g_off[Tn + 1];
__device__ int g_cur[Tn];
__device__ int g_csrc[NEDGE];

// ---------------- PTX helpers ----------------
__device__ __forceinline__ uint32_t smem_u32(const void* p) {
    uint32_t a;
    asm("{ .reg .u64 t; cvta.to.shared.u64 t, %1; cvt.u32.u64 %0, t; }" : "=r"(a) : "l"(p));
    return a;
}
__device__ __forceinline__ void cp_async16(uint32_t dst, const void* src) {
    asm volatile("cp.async.cg.shared.global [%0], [%1], 16;" :: "r"(dst), "l"(src) : "memory");
}
__device__ __forceinline__ void cp_commit() {
    asm volatile("cp.async.commit_group;" ::: "memory");
}
__device__ __forceinline__ void cp_wait1() {
    asm volatile("cp.async.wait_group 1;" ::: "memory");
}
__device__ __forceinline__ void cp_wait0() {
    asm volatile("cp.async.wait_group 0;" ::: "memory");
}
__device__ __forceinline__ void ldmat_x4(uint32_t& r0, uint32_t& r1, uint32_t& r2, uint32_t& r3,
                                         uint32_t addr) {
    asm volatile("ldmatrix.sync.aligned.m8n8.x4.shared.b16 {%0,%1,%2,%3}, [%4];"
                 : "=r"(r0), "=r"(r1), "=r"(r2), "=r"(r3) : "r"(addr));
}
__device__ __forceinline__ void mma_bf16(float* d, const uint32_t* a, const uint32_t* b) {
    asm volatile(
        "mma.sync.aligned.m16n8k16.row.col.f32.bf16.bf16.f32 "
        "{%0,%1,%2,%3}, {%4,%5,%6,%7}, {%8,%9}, {%0,%1,%2,%3};"
        : "+f"(d[0]), "+f"(d[1]), "+f"(d[2]), "+f"(d[3])
        : "r"(a[0]), "r"(a[1]), "r"(a[2]), "r"(a[3]), "r"(b[0]), "r"(b[1]));
}

// SW64 swizzle for 64-byte smem rows (conflict-free for ldmatrix + cp.async)
__device__ __forceinline__ uint32_t sw64(uint32_t off) {
    return off ^ ((off >> 3) & 0x30);
}

// ---------------- bf16 HMMA GEMM (R12-proven: single sync / kt, 3-stage) ----------------
// MODE 0: fp32 plain; MODE 1: bf16 bias+relu; MODE 2: fp32 bias+residual; MODE 3: bf16 plain
template <int N, int K, int MODE>
__global__ __launch_bounds__(256, 2) void gemm_mma(
    const __nv_bfloat16* __restrict__ A,
    const __nv_bfloat16* __restrict__ Bt,
    const float* __restrict__ bias,
    const float* __restrict__ res,
    float* __restrict__ outf,
    __nv_bfloat16* __restrict__ outb)
{
    __shared__ __align__(1024) unsigned char smem[49152]; // 3 stages x (A 8KB | B 8KB)
    const uint32_t sbase = smem_u32(smem);

    int tid = threadIdx.x;
    int wid = tid >> 5;
    int lane = tid & 31;
    int bm = blockIdx.y * 128;
    int bn = blockIdx.x * 128;
    int wm = (wid & 1) * 64;
    int wn = (wid >> 1) * 32;

    float acc[4][4][4];
#pragma unroll
    for (int i = 0; i < 4; i++)
#pragma unroll
        for (int j = 0; j < 4; j++)
#pragma unroll
            for (int d = 0; d < 4; d++) acc[i][j][d] = 0.f;

    const int KT = K / 32;

    auto load_stage = [&](int kt, int s) {
        int k0 = kt * 32;
        uint32_t sA = sbase + s * 16384;
        uint32_t sB = sA + 8192;
#pragma unroll
        for (int i = 0; i < 2; i++) {
            int idx = tid + i * 256;          // 0..511
            int r = idx >> 2, c = idx & 3;
            uint32_t sw = sw64(r * 64 + c * 16);
            cp_async16(sA + sw, A + (size_t)(bm + r) * K + k0 + c * 8);
            cp_async16(sB + sw, Bt + (size_t)(bn + r) * K + k0 + c * 8);
        }
    };

    load_stage(0, 0);
    cp_commit();
    if (KT > 1) { load_stage(1, 1); cp_commit(); }

    for (int kt = 0; kt < KT; kt++) {
        if (kt + 1 < KT) cp_wait1(); else cp_wait0();
        __syncthreads();
        if (kt + 2 < KT) { load_stage(kt + 2, (kt + 2) % 3); cp_commit(); }

        uint32_t sA = sbase + (kt % 3) * 16384;
        uint32_t sB = sA + 8192;
#pragma unroll
        for (int ks = 0; ks < 2; ks++) {
            uint32_t af[4][4];
            uint32_t bf[4][2];
#pragma unroll
            for (int mi = 0; mi < 4; mi++) {
                int row = wm + mi * 16 + (lane & 15);
                int colb = (ks * 16 + ((lane >> 4) << 3)) * 2;
                ldmat_x4(af[mi][0], af[mi][1], af[mi][2], af[mi][3],
                         sA + sw64(row * 64 + colb));
            }
#pragma unroll
            for (int nj = 0; nj < 2; nj++) {
                int nrow = wn + nj * 16 + (lane & 7) + ((lane >> 4) << 3);
                int kcolb = (ks * 16 + (((lane >> 3) & 1) << 3)) * 2;
                uint32_t r0, r1, r2, r3;
                ldmat_x4(r0, r1, r2, r3, sB + sw64(nrow * 64 + kcolb));
                bf[nj * 2][0] = r0; bf[nj * 2][1] = r1;
                bf[nj * 2 + 1][0] = r2; bf[nj * 2 + 1][1] = r3;
            }
#pragma unroll
            for (int mi = 0; mi < 4; mi++)
#pragma unroll
                for (int ni = 0; ni < 4; ni++)
                    mma_bf16(acc[mi][ni], af[mi], bf[ni]);
        }
    }

    int rq = lane >> 2;
    int cq = (lane & 3) * 2;
#pragma unroll
    for (int mi = 0; mi < 4; mi++) {
#pragma unroll
        for (int ni = 0; ni < 4; ni++) {
            int gm = bm + wm + mi * 16 + rq;
            int gn = bn + wn + ni * 8 + cq;
            float v0 = acc[mi][ni][0], v1 = acc[mi][ni][1];
            float v2 = acc[mi][ni][2], v3 = acc[mi][ni][3];
            if (MODE == 0) {
                *(float2*)(outf + (size_t)gm * N + gn) = make_float2(v0, v1);
                *(float2*)(outf + (size_t)(gm + 8) * N + gn) = make_float2(v2, v3);
            } else if (MODE == 1) {
                float b0 = bias[gn], b1 = bias[gn + 1];
                __nv_bfloat162 p0, p1;
                p0.x = __float2bfloat16(fmaxf(v0 + b0, 0.f));
                p0.y = __float2bfloat16(fmaxf(v1 + b1, 0.f));
                p1.x = __float2bfloat16(fmaxf(v2 + b0, 0.f));
                p1.y = __float2bfloat16(fmaxf(v3 + b1, 0.f));
                *(__nv_bfloat162*)(outb + (size_t)gm * N + gn) = p0;
                *(__nv_bfloat162*)(outb + (size_t)(gm + 8) * N + gn) = p1;
            } else if (MODE == 3) {
                __nv_bfloat162 p0, p1;
                p0.x = __float2bfloat16(v0); p0.y = __float2bfloat16(v1);
                p1.x = __float2bfloat16(v2); p1.y = __float2bfloat16(v3);
                *(__nv_bfloat162*)(outb + (size_t)gm * N + gn) = p0;
                *(__nv_bfloat162*)(outb + (size_t)(gm + 8) * N + gn) = p1;
            } else {
                float b0 = bias[gn], b1 = bias[gn + 1];
                float2 r0 = *(const float2*)(res + (size_t)gm * N + gn);
                float2 r1 = *(const float2*)(res + (size_t)(gm + 8) * N + gn);
                *(float2*)(outf + (size_t)gm * N + gn) = make_float2(v0 + b0 + r0.x, v1 + b1 + r0.y);
                *(float2*)(outf + (size_t)(gm + 8) * N + gn) = make_float2(v2 + b0 + r1.x, v3 + b1 + r1.y);
            }
        }
    }
}

// ---------------- weight transpose + fp32->bf16 ----------------
__global__ void transpose_bf16(const float* __restrict__ src, __nv_bfloat16* __restrict__ dst,
                               int Rs, int Cs) {
    __shared__ float t[32][33];
    int c = blockIdx.x * 32 + threadIdx.x;
    int r = blockIdx.y * 32 + threadIdx.y;
    t[threadIdx.y][threadIdx.x] = src[(size_t)r * Cs + c];
    __syncthreads();
    int oc = blockIdx.y * 32 + threadIdx.x;
    int orr = blockIdx.x * 32 + threadIdx.y;
    dst[(size_t)orr * Rs + oc] = __float2bfloat16(t[threadIdx.x][threadIdx.y]);
}

// ---------------- u-vectors: u[h][c] = sum_f W_gat[c][h*64+f] * att[h][f] ----------------
__global__ void attn_u_kernel(const float* __restrict__ W_gat,
                              const float* __restrict__ att_src,
                              const float* __restrict__ att_dst) {
    int c = blockIdx.x * 128 + threadIdx.x;
    if (c >= Cn) return;
    const float* wr = W_gat + (size_t)c * Cn;
#pragma unroll
    for (int h = 0; h < Hn; h++) {
        float s1 = 0.f, s2 = 0.f;
#pragma unroll
        for (int f = 0; f < Fn; f++) {
            float wv = wr[h * Fn + f];
            s1 += wv * att_src[h * Fn + f];
            s2 += wv * att_dst[h * Fn + f];
        }
        g_usrc[h * Cn + c] = s1;
        g_udst[h * Cn + c] = s2;
    }
}

// ---------------- fused LN1 + attention coefficients ----------------
// One block per row (128 threads). Computes xn (bf16 out) AND
// a_src[n][h] = dot(xn_row, usrc[h]), a_dst[n][h] = dot(xn_row, udst[h]) in fp32.
__global__ void ln1_attn_kernel(const float* __restrict__ x, const float* __restrict__ g,
                                const float* __restrict__ b, __nv_bfloat16* __restrict__ out) {
    int row = blockIdx.x;
    int tid = threadIdx.x; // 128
    const float* xr = x + (size_t)row * Cn;
    float v0 = xr[tid], v1 = xr[tid + 128], v2 = xr[tid + 256];
    float s  = v0 + v1 + v2;
    float s2 = v0 * v0 + v1 * v1 + v2 * v2;
#pragma unroll
    for (int o = 16; o; o >>= 1) {
        s  += __shfl_xor_sync(0xffffffffu, s,  o);
        s2 += __shfl_xor_sync(0xffffffffu, s2, o);
    }
    __shared__ float ps[4], ps2[4];
    __shared__ float pdot[12][4];
    if ((tid & 31) == 0) { ps[tid >> 5] = s; ps2[tid >> 5] = s2; }
    __syncthreads();
    s  = ps[0] + ps[1] + ps[2] + ps[3];
    s2 = ps2[0] + ps2[1] + ps2[2] + ps2[3];
    float mu  = s * (1.0f / Cn);
    float var = s2 * (1.0f / Cn) - mu * mu;
    float inv = rsqrtf(var + LN_EPS);
    float xn0 = (v0 - mu) * inv * g[tid]       + b[tid];
    float xn1 = (v1 - mu) * inv * g[tid + 128] + b[tid + 128];
    float xn2 = (v2 - mu) * inv * g[tid + 256] + b[tid + 256];
    __nv_bfloat16* orow = out + (size_t)row * Cn;
    orow[tid]       = __float2bfloat16(xn0);
    orow[tid + 128] = __float2bfloat16(xn1);
    orow[tid + 256] = __float2bfloat16(xn2);

    // 12 dot products: [h<6] src, [h>=6] dst
    float d[12];
#pragma unroll
    for (int h = 0; h < Hn; h++) {
        const float* u1 = g_usrc + h * Cn;
        const float* u2 = g_udst + h * Cn;
        d[h]     = xn0 * u1[tid] + xn1 * u1[tid + 128] + xn2 * u1[tid + 256];
        d[h + 6] = xn0 * u2[tid] + xn1 * u2[tid + 128] + xn2 * u2[tid + 256];
    }
#pragma unroll
    for (int j = 0; j < 12; j++) {
        float v = d[j];
#pragma unroll
        for (int o = 16; o; o >>= 1) v += __shfl_xor_sync(0xffffffffu, v, o);
        if ((tid & 31) == 0) pdot[j][tid >> 5] = v;
    }
    __syncthreads();
    if (tid < 12) {
        float v = pdot[tid][0] + pdot[tid][1] + pdot[tid][2] + pdot[tid][3];
        if (tid < 6) g_asrc[(size_t)row * Hn + tid] = v;
        else         g_adst[(size_t)row * Hn + (tid - 6)] = v;
    }
}

// ---------------- CSR build ----------------
__global__ void zero_cnt_kernel() {
    int i = blockIdx.x * blockDim.x + threadIdx.x;
    if (i <= Tn) g_cnt[i] = 0;
}
__global__ void hist_kernel(const int* __restrict__ edge_dst) {
    int e = blockIdx.x * blockDim.x + threadIdx.x;
    if (e >= NEDGE) return;
    int d = (e < En) ? edge_dst[e] : (e - En);
    atomicAdd(&g_cnt[d], 1);
}
__global__ void scan_kernel() {
    __shared__ int sm[1024];
    int t = threadIdx.x;
    int c0 = g_cnt[4 * t + 0], c1 = g_cnt[4 * t + 1];
    int c2 = g_cnt[4 * t + 2], c3 = g_cnt[4 * t + 3];
    int val = c0 + c1 + c2 + c3;
    sm[t] = val;
    __syncthreads();
    for (int d = 1; d < 1024; d <<= 1) {
        int v = (t >= d) ? sm[t - d] : 0;
        __syncthreads();
        if (t >= d) sm[t] += v;
        __syncthreads();
    }
    int base = sm[t] - val;
    g_off[4 * t + 0] = base;                g_cur[4 * t + 0] = base;
    g_off[4 * t + 1] = base + c0;           g_cur[4 * t + 1] = base + c0;
    g_off[4 * t + 2] = base + c0 + c1;      g_cur[4 * t + 2] = base + c0 + c1;
    g_off[4 * t + 3] = base + c0 + c1 + c2; g_cur[4 * t + 3] = base + c0 + c1 + c2;
    if (t == 1023) g_off[Tn] = sm[1023];
}
__global__ void scatter_kernel(const int* __restrict__ edge_src,
                               const int* __restrict__ edge_dst) {
    int e = blockIdx.x * blockDim.x + threadIdx.x;
    if (e >= NEDGE) return;
    int s, d;
    if (e < En) { s = edge_src[e]; d = edge_dst[e]; }
    else        { s = e - En;      d = e - En; }
    int p = atomicAdd(&g_cur[d], 1);
    g_csrc[p] = s;
}

// ---------------- fused GAT aggregation + LN2 ----------------
// Block per (b,t), 192 threads = 6 warps, warp h handles head h with the proven
// v3 edge loop (quarter-warps, 4 edges/iter). Then block-wide LN2 over the
// 384-value y1 row held in smem; writes y1 (fp32, residual for FFN2) and xnb (bf16).
__global__ __launch_bounds__(192) void gat_ln2_kernel(
    const __nv_bfloat16* __restrict__ Hb,
    const float* __restrict__ asrc,
    const float* __restrict__ adst,
    const float* __restrict__ x,
    const float* __restrict__ bgat,
    const float* __restrict__ ln2g,
    const float* __restrict__ ln2b,
    float* __restrict__ y1,
    __nv_bfloat16* __restrict__ xnb)
{
    __shared__ float y1s[Cn];
    __shared__ float pls[6], pls2[6];

    int n = blockIdx.x;          // b*T + t
    int t = n % Tn;
    int b = n / Tn;
    int wid = threadIdx.x >> 5;  // head
    int lane = threadIdx.x & 31;
    int h = wid;
    int quarter = lane >> 3;
    int sub = lane & 7;
    int beg = g_off[t], end = g_off[t + 1];
    int nb = b * Tn;
    float a_d = adst[(size_t)n * Hn + h];

    float den = 0.f;
    float acc[8] = {};

    for (int e = beg + quarter; e < end; e += 4) {
        int s = g_csrc[e];
        int row = nb + s;
        float al = asrc[(size_t)row * Hn + h] + a_d;
        al = (al >= 0.f) ? al : NEG_SLOPE * al;
        float wgt = __expf(al);
        den += wgt;
        uint4 raw = *(const uint4*)(Hb + (size_t)row * Cn + h * Fn + sub * 8);
        __nv_bfloat162 p0 = *(__nv_bfloat162*)&raw.x;
        __nv_bfloat162 p1 = *(__nv_bfloat162*)&raw.y;
        __nv_bfloat162 p2 = *(__nv_bfloat162*)&raw.z;
        __nv_bfloat162 p3 = *(__nv_bfloat162*)&raw.w;
        acc[0] += wgt * __bfloat162float(p0.x);
        acc[1] += wgt * __bfloat162float(p0.y);
        acc[2] += wgt * __bfloat162float(p1.x);
        acc[3] += wgt * __bfloat162float(p1.y);
        acc[4] += wgt * __bfloat162float(p2.x);
        acc[5] += wgt * __bfloat162float(p2.y);
        acc[6] += wgt * __bfloat162float(p3.x);
        acc[7] += wgt * __bfloat162float(p3.y);
    }
#pragma unroll
    for (int o = 8; o <= 16; o <<= 1) {
        den += __shfl_xor_sync(0xffffffffu, den, o);
#pragma unroll
        for (int j = 0; j < 8; j++)
            acc[j] += __shfl_xor_sync(0xffffffffu, acc[j], o);
    }

    if (quarter == 0) {
        float inv = 1.f / den;
        int c = h * Fn + sub * 8;
        size_t o = (size_t)n * Cn + c;
        float4 x0 = *(const float4*)(x + o);
        float4 x1 = *(const float4*)(x + o + 4);
        float4 bg0 = *(const float4*)(bgat + c);
        float4 bg1 = *(const float4*)(bgat + c + 4);
        float4 r0, r1;
        r0.x = x0.x + acc[0] * inv + bg0.x;
        r0.y = x0.y + acc[1] * inv + bg0.y;
        r0.z = x0.z + acc[2] * inv + bg0.z;
        r0.w = x0.w + acc[3] * inv + bg0.w;
        r1.x = x1.x + acc[4] * inv + bg1.x;
        r1.y = x1.y + acc[5] * inv + bg1.y;
        r1.z = x1.z + acc[6] * inv + bg1.z;
        r1.w = x1.w + acc[7] * inv + bg1.w;
        *(float4*)(y1 + o) = r0;
        *(float4*)(y1 + o + 4) = r1;
        *(float4*)(&y1s[c]) = r0;
        *(float4*)(&y1s[c + 4]) = r1;
    }
    __syncthreads();

    // LN2 over y1s[384]: 192 threads, 2 values each
    int tid = threadIdx.x;
    float u0 = y1s[tid], u1 = y1s[tid + 192];
    float s  = u0 + u1;
    float s2 = u0 * u0 + u1 * u1;
#pragma unroll
    for (int o = 16; o; o >>= 1) {
        s  += __shfl_xor_sync(0xffffffffu, s,  o);
        s2 += __shfl_xor_sync(0xffffffffu, s2, o);
    }
    if (lane == 0) { pls[wid] = s; pls2[wid] = s2; }
    __syncthreads();
    s  = pls[0] + pls[1] + pls[2] + pls[3] + pls[4] + pls[5];
    s2 = pls2[0] + pls2[1] + pls2[2] + pls2[3] + pls2[4] + pls2[5];
    float mu  = s * (1.0f / Cn);
    float var = s2 * (1.0f / Cn) - mu * mu;
    float inv = rsqrtf(var + LN_EPS);
    __nv_bfloat16* orow = xnb + (size_t)n * Cn;
    orow[tid]       = __float2bfloat16((u0 - mu) * inv * ln2g[tid]       + ln2b[tid]);
    orow[tid + 192] = __float2bfloat16((u1 - mu) * inv * ln2g[tid + 192] + ln2b[tid + 192]);
}

// ---------------- launch ----------------
extern "C" void kernel_launch(void* const* d_in, const int* in_sizes, int n_in,
                              void* d_out, int out_size) {
    const float* x        = (const float*)d_in[0];
    const int*   edge     = (const int*)d_in[1];
    const float* W_gat    = (const float*)d_in[2];
    const float* att_src  = (const float*)d_in[3];
    const float* att_dst  = (const float*)d_in[4];
    const float* b_gat    = (const float*)d_in[5];
    const float* ln1_g    = (const float*)d_in[6];
    const float* ln1_b    = (const float*)d_in[7];
    const float* ln2_g    = (const float*)d_in[8];
    const float* ln2_b    = (const float*)d_in[9];
    const float* W1       = (const float*)d_in[10];
    const float* b1       = (const float*)d_in[11];
    const float* W2       = (const float*)d_in[12];
    const float* b2       = (const float*)d_in[13];
    float* out = (float*)d_out;

    const int* edge_src = edge;
    const int* edge_dst = edge + En;

    __nv_bfloat16 *xnb, *hb, *z, *w1t, *w2t, *wgt;
    float *asrc, *adst, *y1;
    cudaGetSymbolAddress((void**)&xnb,  g_xnb);
    cudaGetSymbolAddress((void**)&hb,   g_hb);
    cudaGetSymbolAddress((void**)&asrc, g_asrc);
    cudaGetSymbolAddress((void**)&adst, g_adst);
    cudaGetSymbolAddress((void**)&y1,   g_y1);
    cudaGetSymbolAddress((void**)&z,    g_z);
    cudaGetSymbolAddress((void**)&w1t,  g_w1t);
    cudaGetSymbolAddress((void**)&w2t,  g_w2t);
    cudaGetSymbolAddress((void**)&wgt,  g_wgt);

    // (1) attn_u, (2) fused LN1+attn, (3) W_gat^T, (4) GAT GEMM  <- profiled slot
    attn_u_kernel<<<(Cn + 127) / 128, 128>>>(W_gat, att_src, att_dst);
    ln1_attn_kernel<<<BT, 128>>>(x, ln1_g, ln1_b, xnb);
    transpose_bf16<<<dim3(Cn / 32, Cn / 32), dim3(32, 32)>>>(W_gat, wgt, Cn, Cn);
    gemm_mma<Cn, Cn, 3><<<dim3(Cn / 128, BT / 128), 256>>>(
        xnb, wgt, nullptr, nullptr, nullptr, hb);

    // CSR build (graph shared across batch)
    zero_cnt_kernel<<<(Tn + 256) / 256, 256>>>();
    hist_kernel<<<(NEDGE + 255) / 256, 256>>>(edge_dst);
    scan_kernel<<<1, 1024>>>();
    scatter_kernel<<<(NEDGE + 255) / 256, 256>>>(edge_src, edge_dst);

    // remaining weight transposes
    transpose_bf16<<<dim3(DFF / 32, Cn / 32), dim3(32, 32)>>>(W1, w1t, Cn, DFF);
    transpose_bf16<<<dim3(Cn / 32, DFF / 32), dim3(32, 32)>>>(W2, w2t, DFF, Cn);

    // fused aggregation + LN2: writes y1 and xnb
    gat_ln2_kernel<<<BT, 192>>>(hb, asrc, adst, x, b_gat, ln2_g, ln2_b, y1, xnb);

    // FFN1: Z = relu(xn @ W1 + b1)  (bf16 out)
    gemm_mma<DFF, Cn, 1><<<dim3(DFF / 128, BT / 128), 256>>>(
        xnb, w1t, b1, nullptr, nullptr, z);
    // FFN2: out = Z @ W2 + b2 + y1 (fp32 out)
    gemm_mma<Cn, DFF, 2><<<dim3(Cn / 128, BT / 128), 256>>>(
        z, w2t, b2, y1, out, nullptr);
}

// round 15
// speedup vs baseline: 1.6892x; 1.0036x over previous
#include <cuda_runtime.h>
#include <cuda_bf16.h>
#include <cstdint>

#define Bn 8
#define Tn 4096
#define Cn 384
#define Hn 6
#define Fn 64
#define En 131072
#define DFF 1536
#define BT (Bn * Tn)             // 32768
#define NEDGE (En + Tn)          // 135168
#define NEG_SLOPE 0.2f
#define LN_EPS 1e-5f

// ---------------- scratch (__device__ globals; no allocation) ----------------
__device__ __nv_bfloat16 g_xnb[BT * Cn];     // LN output (bf16), reused LN1/LN2
__device__ __nv_bfloat16 g_hb[BT * Cn];      // GAT projection h (bf16)
__device__ float         g_asrc[BT * Hn];
__device__ float         g_adst[BT * Hn];
__device__ float         g_y1[BT * Cn];      // x + gat_out (residual 1, fp32)
__device__ __nv_bfloat16 g_z[BT * DFF];      // FFN hidden (bf16)
__device__ __nv_bfloat16 g_w1t[DFF * Cn];    // W1^T  [DFF][C]
__device__ __nv_bfloat16 g_w2t[Cn * DFF];    // W2^T  [C][DFF]
__device__ __nv_bfloat16 g_wgt[Cn * Cn];     // W_gat^T
__device__ float         g_usrc[Hn * Cn];    // W_gat @ att_src per head
__device__ float         g_udst[Hn * Cn];
__device__ int g_cnt[Tn + 1];
__device__ int g_off[Tn + 1];
__device__ int g_cur[Tn];
__device__ int g_csrc[NEDGE];

// ---------------- PTX helpers ----------------
__device__ __forceinline__ uint32_t smem_u32(const void* p) {
    uint32_t a;
    asm("{ .reg .u64 t; cvta.to.shared.u64 t, %1; cvt.u32.u64 %0, t; }" : "=r"(a) : "l"(p));
    return a;
}
__device__ __forceinline__ void cp_async16(uint32_t dst, const void* src) {
    asm volatile("cp.async.cg.shared.global [%0], [%1], 16;" :: "r"(dst), "l"(src) : "memory");
}
__device__ __forceinline__ void cp_commit() {
    asm volatile("cp.async.commit_group;" ::: "memory");
}
__device__ __forceinline__ void cp_wait0() {
    asm volatile("cp.async.wait_group 0;" ::: "memory");
}
__device__ __forceinline__ void ldmat_x4(uint32_t& r0, uint32_t& r1, uint32_t& r2, uint32_t& r3,
                                         uint32_t addr) {
    asm volatile("ldmatrix.sync.aligned.m8n8.x4.shared.b16 {%0,%1,%2,%3}, [%4];"
                 : "=r"(r0), "=r"(r1), "=r"(r2), "=r"(r3) : "r"(addr));
}
__device__ __forceinline__ void mma_bf16(float* d, const uint32_t* a, const uint32_t* b) {
    asm volatile(
        "mma.sync.aligned.m16n8k16.row.col.f32.bf16.bf16.f32 "
        "{%0,%1,%2,%3}, {%4,%5,%6,%7}, {%8,%9}, {%0,%1,%2,%3};"
        : "+f"(d[0]), "+f"(d[1]), "+f"(d[2]), "+f"(d[3])
        : "r"(a[0]), "r"(a[1]), "r"(a[2]), "r"(a[3]), "r"(b[0]), "r"(b[1]));
}

// SW128 swizzle for 128-byte smem rows (conflict-free for ldmatrix + cp.async)
__device__ __forceinline__ uint32_t sw128(uint32_t off) {
    return off ^ ((off >> 3) & 0x70);
}

// ---------------- bf16 HMMA GEMM: BK=64, 2-stage, ONE sync+wait per kt ----------------
// MODE 0: fp32 plain; MODE 1: bf16 bias+relu; MODE 2: fp32 bias+residual; MODE 3: bf16 plain
// 128x128 CTA tile, 8 warps (2M x 4N), warp tile 64x32, 64KB dynamic smem.
// Loop: wait0 -> sync -> prefetch(kt+1 into (kt+1)&1) -> compute(kt from kt&1, 4 ks-blocks).
// Overwrite safe: stage (kt+1)&1 last read in compute kt-1; all warps past this kt's sync.
template <int N, int K, int MODE>
__global__ __launch_bounds__(256, 2) void gemm_mma(
    const __nv_bfloat16* __restrict__ A,
    const __nv_bfloat16* __restrict__ Bt,
    const float* __restrict__ bias,
    const float* __restrict__ res,
    float* __restrict__ outf,
    __nv_bfloat16* __restrict__ outb)
{
    extern __shared__ __align__(1024) unsigned char smem[]; // 2 stages x (A 16KB | B 16KB)
    const uint32_t sbase = smem_u32(smem);

    int tid = threadIdx.x;
    int wid = tid >> 5;
    int lane = tid & 31;
    int bm = blockIdx.y * 128;
    int bn = blockIdx.x * 128;
    int wm = (wid & 1) * 64;
    int wn = (wid >> 1) * 32;

    float acc[4][4][4];
#pragma unroll
    for (int i = 0; i < 4; i++)
#pragma unroll
        for (int j = 0; j < 4; j++)
#pragma unroll
            for (int d = 0; d < 4; d++) acc[i][j][d] = 0.f;

    const int KT = K / 64;

    auto load_stage = [&](int kt, int s) {
        int k0 = kt * 64;
        uint32_t sA = sbase + s * 32768;
        uint32_t sB = sA + 16384;
#pragma unroll
        for (int i = 0; i < 4; i++) {
            int idx = tid + i * 256;          // 0..1023
            int r = idx >> 3, c = idx & 7;    // 128 rows x 8 chunks of 16B
            uint32_t sw = sw128(r * 128 + c * 16);
            cp_async16(sA + sw, A + (size_t)(bm + r) * K + k0 + c * 8);
            cp_async16(sB + sw, Bt + (size_t)(bn + r) * K + k0 + c * 8);
        }
    };

    load_stage(0, 0);
    cp_commit();

    for (int kt = 0; kt < KT; kt++) {
        cp_wait0();
        __syncthreads();
        if (kt + 1 < KT) { load_stage(kt + 1, (kt + 1) & 1); cp_commit(); }

        uint32_t sA = sbase + (kt & 1) * 32768;
        uint32_t sB = sA + 16384;
#pragma unroll
        for (int ks = 0; ks < 4; ks++) {
            uint32_t af[4][4];
            uint32_t bf[4][2];
#pragma unroll
            for (int mi = 0; mi < 4; mi++) {
                int row = wm + mi * 16 + (lane & 15);
                int colb = ks * 32 + ((lane >> 4) << 4);
                ldmat_x4(af[mi][0], af[mi][1], af[mi][2], af[mi][3],
                         sA + sw128(row * 128 + colb));
            }
#pragma unroll
            for (int nj = 0; nj < 2; nj++) {
                int nrow = wn + nj * 16 + (lane & 7) + ((lane >> 4) << 3);
                int kcolb = ks * 32 + (((lane >> 3) & 1) << 4);
                uint32_t r0, r1, r2, r3;
                ldmat_x4(r0, r1, r2, r3, sB + sw128(nrow * 128 + kcolb));
                bf[nj * 2][0] = r0; bf[nj * 2][1] = r1;
                bf[nj * 2 + 1][0] = r2; bf[nj * 2 + 1][1] = r3;
            }
#pragma unroll
            for (int mi = 0; mi < 4; mi++)
#pragma unroll
                for (int ni = 0; ni < 4; ni++)
                    mma_bf16(acc[mi][ni], af[mi], bf[ni]);
        }
    }

    int rq = lane >> 2;
    int cq = (lane & 3) * 2;
#pragma unroll
    for (int mi = 0; mi < 4; mi++) {
#pragma unroll
        for (int ni = 0; ni < 4; ni++) {
            int gm = bm + wm + mi * 16 + rq;
            int gn = bn + wn + ni * 8 + cq;
            float v0 = acc[mi][ni][0], v1 = acc[mi][ni][1];
            float v2 = acc[mi][ni][2], v3 = acc[mi][ni][3];
            if (MODE == 0) {
                *(float2*)(outf + (size_t)gm * N + gn) = make_float2(v0, v1);
                *(float2*)(outf + (size_t)(gm + 8) * N + gn) = make_float2(v2, v3);
            } else if (MODE == 1) {
                float b0 = bias[gn], b1 = bias[gn + 1];
                __nv_bfloat162 p0, p1;
                p0.x = __float2bfloat16(fmaxf(v0 + b0, 0.f));
                p0.y = __float2bfloat16(fmaxf(v1 + b1, 0.f));
                p1.x = __float2bfloat16(fmaxf(v2 + b0, 0.f));
                p1.y = __float2bfloat16(fmaxf(v3 + b1, 0.f));
                *(__nv_bfloat162*)(outb + (size_t)gm * N + gn) = p0;
                *(__nv_bfloat162*)(outb + (size_t)(gm + 8) * N + gn) = p1;
            } else if (MODE == 3) {
                __nv_bfloat162 p0, p1;
                p0.x = __float2bfloat16(v0); p0.y = __float2bfloat16(v1);
                p1.x = __float2bfloat16(v2); p1.y = __float2bfloat16(v3);
                *(__nv_bfloat162*)(outb + (size_t)gm * N + gn) = p0;
                *(__nv_bfloat162*)(outb + (size_t)(gm + 8) * N + gn) = p1;
            } else {
                float b0 = bias[gn], b1 = bias[gn + 1];
                float2 r0 = *(const float2*)(res + (size_t)gm * N + gn);
                float2 r1 = *(const float2*)(res + (size_t)(gm + 8) * N + gn);
                *(float2*)(outf + (size_t)gm * N + gn) = make_float2(v0 + b0 + r0.x, v1 + b1 + r0.y);
                *(float2*)(outf + (size_t)(gm + 8) * N + gn) = make_float2(v2 + b0 + r1.x, v3 + b1 + r1.y);
            }
        }
    }
}

#define GEMM_SMEM_DYN 65536

// ---------------- weight transpose + fp32->bf16 ----------------
__global__ void transpose_bf16(const float* __restrict__ src, __nv_bfloat16* __restrict__ dst,
                               int Rs, int Cs) {
    __shared__ float t[32][33];
    int c = blockIdx.x * 32 + threadIdx.x;
    int r = blockIdx.y * 32 + threadIdx.y;
    t[threadIdx.y][threadIdx.x] = src[(size_t)r * Cs + c];
    __syncthreads();
    int oc = blockIdx.y * 32 + threadIdx.x;
    int orr = blockIdx.x * 32 + threadIdx.y;
    dst[(size_t)orr * Rs + oc] = __float2bfloat16(t[threadIdx.x][threadIdx.y]);
}

// ---------------- u-vectors ----------------
__global__ void attn_u_kernel(const float* __restrict__ W_gat,
                              const float* __restrict__ att_src,
                              const float* __restrict__ att_dst) {
    int c = blockIdx.x * 128 + threadIdx.x;
    if (c >= Cn) return;
    const float* wr = W_gat + (size_t)c * Cn;
#pragma unroll
    for (int h = 0; h < Hn; h++) {
        float s1 = 0.f, s2 = 0.f;
#pragma unroll
        for (int f = 0; f < Fn; f++) {
            float wv = wr[h * Fn + f];
            s1 += wv * att_src[h * Fn + f];
            s2 += wv * att_dst[h * Fn + f];
        }
        g_usrc[h * Cn + c] = s1;
        g_udst[h * Cn + c] = s2;
    }
}

// ---------------- fused LN1 + attention coefficients ----------------
__global__ void ln1_attn_kernel(const float* __restrict__ x, const float* __restrict__ g,
                                const float* __restrict__ b, __nv_bfloat16* __restrict__ out) {
    int row = blockIdx.x;
    int tid = threadIdx.x; // 128
    const float* xr = x + (size_t)row * Cn;
    float v0 = xr[tid], v1 = xr[tid + 128], v2 = xr[tid + 256];
    float s  = v0 + v1 + v2;
    float s2 = v0 * v0 + v1 * v1 + v2 * v2;
#pragma unroll
    for (int o = 16; o; o >>= 1) {
        s  += __shfl_xor_sync(0xffffffffu, s,  o);
        s2 += __shfl_xor_sync(0xffffffffu, s2, o);
    }
    __shared__ float ps[4], ps2[4];
    __shared__ float pdot[12][4];
    if ((tid & 31) == 0) { ps[tid >> 5] = s; ps2[tid >> 5] = s2; }
    __syncthreads();
    s  = ps[0] + ps[1] + ps[2] + ps[3];
    s2 = ps2[0] + ps2[1] + ps2[2] + ps2[3];
    float mu  = s * (1.0f / Cn);
    float var = s2 * (1.0f / Cn) - mu * mu;
    float inv = rsqrtf(var + LN_EPS);
    float xn0 = (v0 - mu) * inv * g[tid]       + b[tid];
    float xn1 = (v1 - mu) * inv * g[tid + 128] + b[tid + 128];
    float xn2 = (v2 - mu) * inv * g[tid + 256] + b[tid + 256];
    __nv_bfloat16* orow = out + (size_t)row * Cn;
    orow[tid]       = __float2bfloat16(xn0);
    orow[tid + 128] = __float2bfloat16(xn1);
    orow[tid + 256] = __float2bfloat16(xn2);

    float d[12];
#pragma unroll
    for (int h = 0; h < Hn; h++) {
        const float* u1 = g_usrc + h * Cn;
        const float* u2 = g_udst + h * Cn;
        d[h]     = xn0 * u1[tid] + xn1 * u1[tid + 128] + xn2 * u1[tid + 256];
        d[h + 6] = xn0 * u2[tid] + xn1 * u2[tid + 128] + xn2 * u2[tid + 256];
    }
#pragma unroll
    for (int j = 0; j < 12; j++) {
        float v = d[j];
#pragma unroll
        for (int o = 16; o; o >>= 1) v += __shfl_xor_sync(0xffffffffu, v, o);
        if ((tid & 31) == 0) pdot[j][tid >> 5] = v;
    }
    __syncthreads();
    if (tid < 12) {
        float v = pdot[tid][0] + pdot[tid][1] + pdot[tid][2] + pdot[tid][3];
        if (tid < 6) g_asrc[(size_t)row * Hn + tid] = v;
        else         g_adst[(size_t)row * Hn + (tid - 6)] = v;
    }
}

// ---------------- CSR build ----------------
__global__ void zero_cnt_kernel() {
    int i = blockIdx.x * blockDim.x + threadIdx.x;
    if (i <= Tn) g_cnt[i] = 0;
}
__global__ void hist_kernel(const int* __restrict__ edge_dst) {
    int e = blockIdx.x * blockDim.x + threadIdx.x;
    if (e >= NEDGE) return;
    int d = (e < En) ? edge_dst[e] : (e - En);
    atomicAdd(&g_cnt[d], 1);
}
__global__ void scan_kernel() {
    __shared__ int sm[1024];
    int t = threadIdx.x;
    int c0 = g_cnt[4 * t + 0], c1 = g_cnt[4 * t + 1];
    int c2 = g_cnt[4 * t + 2], c3 = g_cnt[4 * t + 3];
    int val = c0 + c1 + c2 + c3;
    sm[t] = val;
    __syncthreads();
    for (int d = 1; d < 1024; d <<= 1) {
        int v = (t >= d) ? sm[t - d] : 0;
        __syncthreads();
        if (t >= d) sm[t] += v;
        __syncthreads();
    }
    int base = sm[t] - val;
    g_off[4 * t + 0] = base;                g_cur[4 * t + 0] = base;
    g_off[4 * t + 1] = base + c0;           g_cur[4 * t + 1] = base + c0;
    g_off[4 * t + 2] = base + c0 + c1;      g_cur[4 * t + 2] = base + c0 + c1;
    g_off[4 * t + 3] = base + c0 + c1 + c2; g_cur[4 * t + 3] = base + c0 + c1 + c2;
    if (t == 1023) g_off[Tn] = sm[1023];
}
__global__ void scatter_kernel(const int* __restrict__ edge_src,
                               const int* __restrict__ edge_dst) {
    int e = blockIdx.x * blockDim.x + threadIdx.x;
    if (e >= NEDGE) return;
    int s, d;
    if (e < En) { s = edge_src[e]; d = edge_dst[e]; }
    else        { s = e - En;      d = e - En; }
    int p = atomicAdd(&g_cur[d], 1);
    g_csrc[p] = s;
}

// ---------------- fused GAT aggregation + LN2 ----------------
__global__ __launch_bounds__(192) void gat_ln2_kernel(
    const __nv_bfloat16* __restrict__ Hb,
    const float* __restrict__ asrc,
    const float* __restrict__ adst,
    const float* __restrict__ x,
    const float* __restrict__ bgat,
    const float* __restrict__ ln2g,
    const float* __restrict__ ln2b,
    float* __restrict__ y1,
    __nv_bfloat16* __restrict__ xnb)
{
    __shared__ float y1s[Cn];
    __shared__ float pls[6], pls2[6];

    int n = blockIdx.x;          // b*T + t
    int t = n % Tn;
    int b = n / Tn;
    int wid = threadIdx.x >> 5;  // head
    int lane = threadIdx.x & 31;
    int h = wid;
    int quarter = lane >> 3;
    int sub = lane & 7;
    int beg = g_off[t], end = g_off[t + 1];
    int nb = b * Tn;
    float a_d = adst[(size_t)n * Hn + h];

    float den = 0.f;
    float acc[8] = {};

    for (int e = beg + quarter; e < end; e += 4) {
        int s = g_csrc[e];
        int row = nb + s;
        float al = asrc[(size_t)row * Hn + h] + a_d;
        al = (al >= 0.f) ? al : NEG_SLOPE * al;
        float wgt = __expf(al);
        den += wgt;
        uint4 raw = *(const uint4*)(Hb + (size_t)row * Cn + h * Fn + sub * 8);
        __nv_bfloat162 p0 = *(__nv_bfloat162*)&raw.x;
        __nv_bfloat162 p1 = *(__nv_bfloat162*)&raw.y;
        __nv_bfloat162 p2 = *(__nv_bfloat162*)&raw.z;
        __nv_bfloat162 p3 = *(__nv_bfloat162*)&raw.w;
        acc[0] += wgt * __bfloat162float(p0.x);
        acc[1] += wgt * __bfloat162float(p0.y);
        acc[2] += wgt * __bfloat162float(p1.x);
        acc[3] += wgt * __bfloat162float(p1.y);
        acc[4] += wgt * __bfloat162float(p2.x);
        acc[5] += wgt * __bfloat162float(p2.y);
        acc[6] += wgt * __bfloat162float(p3.x);
        acc[7] += wgt * __bfloat162float(p3.y);
    }
#pragma unroll
    for (int o = 8; o <= 16; o <<= 1) {
        den += __shfl_xor_sync(0xffffffffu, den, o);
#pragma unroll
        for (int j = 0; j < 8; j++)
            acc[j] += __shfl_xor_sync(0xffffffffu, acc[j], o);
    }

    if (quarter == 0) {
        float inv = 1.f / den;
        int c = h * Fn + sub * 8;
        size_t o = (size_t)n * Cn + c;
        float4 x0 = *(const float4*)(x + o);
        float4 x1 = *(const float4*)(x + o + 4);
        float4 bg0 = *(const float4*)(bgat + c);
        float4 bg1 = *(const float4*)(bgat + c + 4);
        float4 r0, r1;
        r0.x = x0.x + acc[0] * inv + bg0.x;
        r0.y = x0.y + acc[1] * inv + bg0.y;
        r0.z = x0.z + acc[2] * inv + bg0.z;
        r0.w = x0.w + acc[3] * inv + bg0.w;
        r1.x = x1.x + acc[4] * inv + bg1.x;
        r1.y = x1.y + acc[5] * inv + bg1.y;
        r1.z = x1.z + acc[6] * inv + bg1.z;
        r1.w = x1.w + acc[7] * inv + bg1.w;
        *(float4*)(y1 + o) = r0;
        *(float4*)(y1 + o + 4) = r1;
        *(float4*)(&y1s[c]) = r0;
        *(float4*)(&y1s[c + 4]) = r1;
    }
    __syncthreads();

    int tid = threadIdx.x;
    float u0 = y1s[tid], u1 = y1s[tid + 192];
    float s  = u0 + u1;
    float s2 = u0 * u0 + u1 * u1;
#pragma unroll
    for (int o = 16; o; o >>= 1) {
        s  += __shfl_xor_sync(0xffffffffu, s,  o);
        s2 += __shfl_xor_sync(0xffffffffu, s2, o);
    }
    if (lane == 0) { pls[wid] = s; pls2[wid] = s2; }
    __syncthreads();
    s  = pls[0] + pls[1] + pls[2] + pls[3] + pls[4] + pls[5];
    s2 = pls2[0] + pls2[1] + pls2[2] + pls2[3] + pls2[4] + pls2[5];
    float mu  = s * (1.0f / Cn);
    float var = s2 * (1.0f / Cn) - mu * mu;
    float inv = rsqrtf(var + LN_EPS);
    __nv_bfloat16* orow = xnb + (size_t)n * Cn;
    orow[tid]       = __float2bfloat16((u0 - mu) * inv * ln2g[tid]       + ln2b[tid]);
    orow[tid + 192] = __float2bfloat16((u1 - mu) * inv * ln2g[tid + 192] + ln2b[tid + 192]);
}

// ---------------- launch ----------------
extern "C" void kernel_launch(void* const* d_in, const int* in_sizes, int n_in,
                              void* d_out, int out_size) {
    const float* x        = (const float*)d_in[0];
    const int*   edge     = (const int*)d_in[1];
    const float* W_gat    = (const float*)d_in[2];
    const float* att_src  = (const float*)d_in[3];
    const float* att_dst  = (const float*)d_in[4];
    const float* b_gat    = (const float*)d_in[5];
    const float* ln1_g    = (const float*)d_in[6];
    const float* ln1_b    = (const float*)d_in[7];
    const float* ln2_g    = (const float*)d_in[8];
    const float* ln2_b    = (const float*)d_in[9];
    const float* W1       = (const float*)d_in[10];
    const float* b1       = (const float*)d_in[11];
    const float* W2       = (const float*)d_in[12];
    const float* b2       = (const float*)d_in[13];
    float* out = (float*)d_out;

    const int* edge_src = edge;
    const int* edge_dst = edge + En;

    __nv_bfloat16 *xnb, *hb, *z, *w1t, *w2t, *wgt;
    float *asrc, *adst, *y1;
    cudaGetSymbolAddress((void**)&xnb,  g_xnb);
    cudaGetSymbolAddress((void**)&hb,   g_hb);
    cudaGetSymbolAddress((void**)&asrc, g_asrc);
    cudaGetSymbolAddress((void**)&adst, g_adst);
    cudaGetSymbolAddress((void**)&y1,   g_y1);
    cudaGetSymbolAddress((void**)&z,    g_z);
    cudaGetSymbolAddress((void**)&w1t,  g_w1t);
    cudaGetSymbolAddress((void**)&w2t,  g_w2t);
    cudaGetSymbolAddress((void**)&wgt,  g_wgt);

    // opt-in to 64KB dynamic smem for the three GEMM instantiations (idempotent)
    cudaFuncSetAttribute(gemm_mma<Cn, Cn, 3>,
                         cudaFuncAttributeMaxDynamicSharedMemorySize, GEMM_SMEM_DYN);
    cudaFuncSetAttribute(gemm_mma<DFF, Cn, 1>,
                         cudaFuncAttributeMaxDynamicSharedMemorySize, GEMM_SMEM_DYN);
    cudaFuncSetAttribute(gemm_mma<Cn, DFF, 2>,
                         cudaFuncAttributeMaxDynamicSharedMemorySize, GEMM_SMEM_DYN);

    // (1) attn_u, (2) fused LN1+attn, (3) W_gat^T, (4) GAT GEMM  <- profiled slot
    attn_u_kernel<<<(Cn + 127) / 128, 128>>>(W_gat, att_src, att_dst);
    ln1_attn_kernel<<<BT, 128>>>(x, ln1_g, ln1_b, xnb);
    transpose_bf16<<<dim3(Cn / 32, Cn / 32), dim3(32, 32)>>>(W_gat, wgt, Cn, Cn);
    gemm_mma<Cn, Cn, 3><<<dim3(Cn / 128, BT / 128), 256, GEMM_SMEM_DYN>>>(
        xnb, wgt, nullptr, nullptr, nullptr, hb);

    // CSR build (graph shared across batch)
    zero_cnt_kernel<<<(Tn + 256) / 256, 256>>>();
    hist_kernel<<<(NEDGE + 255) / 256, 256>>>(edge_dst);
    scan_kernel<<<1, 1024>>>();
    scatter_kernel<<<(NEDGE + 255) / 256, 256>>>(edge_src, edge_dst);

    // remaining weight transposes
    transpose_bf16<<<dim3(DFF / 32, Cn / 32), dim3(32, 32)>>>(W1, w1t, Cn, DFF);
    transpose_bf16<<<dim3(Cn / 32, DFF / 32), dim3(32, 32)>>>(W2, w2t, DFF, Cn);

    // fused aggregation + LN2: writes y1 and xnb
    gat_ln2_kernel<<<BT, 192>>>(hb, asrc, adst, x, b_gat, ln2_g, ln2_b, y1, xnb);

    // FFN1: Z = relu(xn @ W1 + b1)  (bf16 out)
    gemm_mma<DFF, Cn, 1><<<dim3(DFF / 128, BT / 128), 256, GEMM_SMEM_DYN>>>(
        xnb, w1t, b1, nullptr, nullptr, z);
    // FFN2: out = Z @ W2 + b2 + y1 (fp32 out)
    gemm_mma<Cn, DFF, 2><<<dim3(Cn / 128, BT / 128), 256, GEMM_SMEM_DYN>>>(
        z, w2t, b2, y1, out, nullptr);
}

// round 17
// speedup vs baseline: 1.7365x; 1.0280x over previous
#include <cuda_runtime.h>
#include <cuda_bf16.h>
#include <cstdint>

#define Bn 8
#define Tn 4096
#define Cn 384
#define Hn 6
#define Fn 64
#define En 131072
#define DFF 1536
#define BT (Bn * Tn)             // 32768
#define NEDGE (En + Tn)          // 135168
#define NEG_SLOPE 0.2f
#define LN_EPS 1e-5f

// ---------------- scratch (__device__ globals; no allocation) ----------------
__device__ __nv_bfloat16 g_xnb[BT * Cn];     // LN output (bf16), reused LN1/LN2
__device__ __nv_bfloat16 g_hb[BT * Cn];      // GAT projection h (bf16)
__device__ float         g_asrc[BT * Hn];
__device__ float         g_adst[BT * Hn];
__device__ float         g_y1[BT * Cn];      // x + gat_out (residual 1, fp32)
__device__ __nv_bfloat16 g_z[BT * DFF];      // FFN hidden (bf16)
__device__ __nv_bfloat16 g_w1t[DFF * Cn];    // W1^T  [DFF][C]
__device__ __nv_bfloat16 g_w2t[Cn * DFF];    // W2^T  [C][DFF]
__device__ __nv_bfloat16 g_wgt[Cn * Cn];     // W_gat^T
__device__ float         g_usrc[Hn * Cn];    // W_gat @ att_src per head
__device__ float         g_udst[Hn * Cn];
__device__ int g_cnt[Tn + 1];
__device__ int g_off[Tn + 1];
__device__ int g_cur[Tn];
__device__ int g_csrc[NEDGE];

// ---------------- PTX helpers ----------------
__device__ __forceinline__ uint32_t smem_u32(const void* p) {
    uint32_t a;
    asm("{ .reg .u64 t; cvta.to.shared.u64 t, %1; cvt.u32.u64 %0, t; }" : "=r"(a) : "l"(p));
    return a;
}
__device__ __forceinline__ void cp_async16(uint32_t dst, const void* src) {
    asm volatile("cp.async.cg.shared.global [%0], [%1], 16;" :: "r"(dst), "l"(src) : "memory");
}
__device__ __forceinline__ void cp_commit() {
    asm volatile("cp.async.commit_group;" ::: "memory");
}
__device__ __forceinline__ void cp_wait1() {
    asm volatile("cp.async.wait_group 1;" ::: "memory");
}
__device__ __forceinline__ void cp_wait0() {
    asm volatile("cp.async.wait_group 0;" ::: "memory");
}
__device__ __forceinline__ void ldmat_x4(uint32_t& r0, uint32_t& r1, uint32_t& r2, uint32_t& r3,
                                         uint32_t addr) {
    asm volatile("ldmatrix.sync.aligned.m8n8.x4.shared.b16 {%0,%1,%2,%3}, [%4];"
                 : "=r"(r0), "=r"(r1), "=r"(r2), "=r"(r3) : "r"(addr));
}
__device__ __forceinline__ void mma_bf16(float* d, const uint32_t* a, const uint32_t* b) {
    asm volatile(
        "mma.sync.aligned.m16n8k16.row.col.f32.bf16.bf16.f32 "
        "{%0,%1,%2,%3}, {%4,%5,%6,%7}, {%8,%9}, {%0,%1,%2,%3};"
        : "+f"(d[0]), "+f"(d[1]), "+f"(d[2]), "+f"(d[3])
        : "r"(a[0]), "r"(a[1]), "r"(a[2]), "r"(a[3]), "r"(b[0]), "r"(b[1]));
}

__device__ __forceinline__ uint32_t sw64(uint32_t off) {
    return off ^ ((off >> 3) & 0x30);
}
__device__ __forceinline__ uint32_t sw128(uint32_t off) {
    return off ^ ((off >> 3) & 0x70);
}

// ---------------- epilogue (shared by both GEMM variants) ----------------
template <int N, int MODE>
__device__ __forceinline__ void gemm_epilogue(
    float acc[4][4][4], int bm, int bn, int wm, int wn, int lane,
    const float* __restrict__ bias, const float* __restrict__ res,
    float* __restrict__ outf, __nv_bfloat16* __restrict__ outb)
{
    int rq = lane >> 2;
    int cq = (lane & 3) * 2;
#pragma unroll
    for (int mi = 0; mi < 4; mi++) {
#pragma unroll
        for (int ni = 0; ni < 4; ni++) {
            int gm = bm + wm + mi * 16 + rq;
            int gn = bn + wn + ni * 8 + cq;
            float v0 = acc[mi][ni][0], v1 = acc[mi][ni][1];
            float v2 = acc[mi][ni][2], v3 = acc[mi][ni][3];
            if (MODE == 0) {
                *(float2*)(outf + (size_t)gm * N + gn) = make_float2(v0, v1);
                *(float2*)(outf + (size_t)(gm + 8) * N + gn) = make_float2(v2, v3);
            } else if (MODE == 1) {
                float b0 = bias[gn], b1 = bias[gn + 1];
                __nv_bfloat162 p0, p1;
                p0.x = __float2bfloat16(fmaxf(v0 + b0, 0.f));
                p0.y = __float2bfloat16(fmaxf(v1 + b1, 0.f));
                p1.x = __float2bfloat16(fmaxf(v2 + b0, 0.f));
                p1.y = __float2bfloat16(fmaxf(v3 + b1, 0.f));
                *(__nv_bfloat162*)(outb + (size_t)gm * N + gn) = p0;
                *(__nv_bfloat162*)(outb + (size_t)(gm + 8) * N + gn) = p1;
            } else if (MODE == 3) {
                __nv_bfloat162 p0, p1;
                p0.x = __float2bfloat16(v0); p0.y = __float2bfloat16(v1);
                p1.x = __float2bfloat16(v2); p1.y = __float2bfloat16(v3);
                *(__nv_bfloat162*)(outb + (size_t)gm * N + gn) = p0;
                *(__nv_bfloat162*)(outb + (size_t)(gm + 8) * N + gn) = p1;
            } else {
                float b0 = bias[gn], b1 = bias[gn + 1];
                float2 r0 = *(const float2*)(res + (size_t)gm * N + gn);
                float2 r1 = *(const float2*)(res + (size_t)(gm + 8) * N + gn);
                *(float2*)(outf + (size_t)gm * N + gn) = make_float2(v0 + b0 + r0.x, v1 + b1 + r0.y);
                *(float2*)(outf + (size_t)(gm + 8) * N + gn) = make_float2(v2 + b0 + r1.x, v3 + b1 + r1.y);
            }
        }
    }
}

// ---------------- GEMM variant A (K=384): BK=32, 3-stage, single sync/kt ----------------
// (R12/R14-measured: 35.3us on the GAT GEMM)
template <int N, int K, int MODE>
__global__ __launch_bounds__(256, 2) void gemm_mma3(
    const __nv_bfloat16* __restrict__ A,
    const __nv_bfloat16* __restrict__ Bt,
    const float* __restrict__ bias,
    const float* __restrict__ res,
    float* __restrict__ outf,
    __nv_bfloat16* __restrict__ outb)
{
    __shared__ __align__(1024) unsigned char smem[49152]; // 3 stages x (A 8KB | B 8KB)
    const uint32_t sbase = smem_u32(smem);

    int tid = threadIdx.x;
    int wid = tid >> 5;
    int lane = tid & 31;
    int bm = blockIdx.y * 128;
    int bn = blockIdx.x * 128;
    int wm = (wid & 1) * 64;
    int wn = (wid >> 1) * 32;

    float acc[4][4][4];
#pragma unroll
    for (int i = 0; i < 4; i++)
#pragma unroll
        for (int j = 0; j < 4; j++)
#pragma unroll
            for (int d = 0; d < 4; d++) acc[i][j][d] = 0.f;

    const int KT = K / 32;

    auto load_stage = [&](int kt, int s) {
        int k0 = kt * 32;
        uint32_t sA = sbase + s * 16384;
        uint32_t sB = sA + 8192;
#pragma unroll
        for (int i = 0; i < 2; i++) {
            int idx = tid + i * 256;
            int r = idx >> 2, c = idx & 3;
            uint32_t sw = sw64(r * 64 + c * 16);
            cp_async16(sA + sw, A + (size_t)(bm + r) * K + k0 + c * 8);
            cp_async16(sB + sw, Bt + (size_t)(bn + r) * K + k0 + c * 8);
        }
    };

    load_stage(0, 0);
    cp_commit();
    if (KT > 1) { load_stage(1, 1); cp_commit(); }

    for (int kt = 0; kt < KT; kt++) {
        if (kt + 1 < KT) cp_wait1(); else cp_wait0();
        __syncthreads();
        if (kt + 2 < KT) { load_stage(kt + 2, (kt + 2) % 3); cp_commit(); }

        uint32_t sA = sbase + (kt % 3) * 16384;
        uint32_t sB = sA + 8192;
#pragma unroll
        for (int ks = 0; ks < 2; ks++) {
            uint32_t af[4][4];
            uint32_t bf[4][2];
#pragma unroll
            for (int mi = 0; mi < 4; mi++) {
                int row = wm + mi * 16 + (lane & 15);
                int colb = (ks * 16 + ((lane >> 4) << 3)) * 2;
                ldmat_x4(af[mi][0], af[mi][1], af[mi][2], af[mi][3],
                         sA + sw64(row * 64 + colb));
            }
#pragma unroll
            for (int nj = 0; nj < 2; nj++) {
                int nrow = wn + nj * 16 + (lane & 7) + ((lane >> 4) << 3);
                int kcolb = (ks * 16 + (((lane >> 3) & 1) << 3)) * 2;
                uint32_t r0, r1, r2, r3;
                ldmat_x4(r0, r1, r2, r3, sB + sw64(nrow * 64 + kcolb));
                bf[nj * 2][0] = r0; bf[nj * 2][1] = r1;
                bf[nj * 2 + 1][0] = r2; bf[nj * 2 + 1][1] = r3;
            }
#pragma unroll
            for (int mi = 0; mi < 4; mi++)
#pragma unroll
                for (int ni = 0; ni < 4; ni++)
                    mma_bf16(acc[mi][ni], af[mi], bf[ni]);
        }
    }

    gemm_epilogue<N, MODE>(acc, bm, bn, wm, wn, lane, bias, res, outf, outb);
}

// ---------------- GEMM variant B (K=1536): BK=64, 2-stage, single sync/kt ----------------
// (R15-measured: drove the FFN gain; fewer barriers per FLOP for long K)
template <int N, int K, int MODE>
__global__ __launch_bounds__(256, 2) void gemm_mma64(
    const __nv_bfloat16* __restrict__ A,
    const __nv_bfloat16* __restrict__ Bt,
    const float* __restrict__ bias,
    const float* __restrict__ res,
    float* __restrict__ outf,
    __nv_bfloat16* __restrict__ outb)
{
    extern __shared__ __align__(1024) unsigned char smem[]; // 2 stages x (A 16KB | B 16KB)
    const uint32_t sbase = smem_u32(smem);

    int tid = threadIdx.x;
    int wid = tid >> 5;
    int lane = tid & 31;
    int bm = blockIdx.y * 128;
    int bn = blockIdx.x * 128;
    int wm = (wid & 1) * 64;
    int wn = (wid >> 1) * 32;

    float acc[4][4][4];
#pragma unroll
    for (int i = 0; i < 4; i++)
#pragma unroll
        for (int j = 0; j < 4; j++)
#pragma unroll
            for (int d = 0; d < 4; d++) acc[i][j][d] = 0.f;

    const int KT = K / 64;

    auto load_stage = [&](int kt, int s) {
        int k0 = kt * 64;
        uint32_t sA = sbase + s * 32768;
        uint32_t sB = sA + 16384;
#pragma unroll
        for (int i = 0; i < 4; i++) {
            int idx = tid + i * 256;          // 0..1023
            int r = idx >> 3, c = idx & 7;
            uint32_t sw = sw128(r * 128 + c * 16);
            cp_async16(sA + sw, A + (size_t)(bm + r) * K + k0 + c * 8);
            cp_async16(sB + sw, Bt + (size_t)(bn + r) * K + k0 + c * 8);
        }
    };

    load_stage(0, 0);
    cp_commit();

    for (int kt = 0; kt < KT; kt++) {
        cp_wait0();
        __syncthreads();
        if (kt + 1 < KT) { load_stage(kt + 1, (kt + 1) & 1); cp_commit(); }

        uint32_t sA = sbase + (kt & 1) * 32768;
        uint32_t sB = sA + 16384;
#pragma unroll
        for (int ks = 0; ks < 4; ks++) {
            uint32_t af[4][4];
            uint32_t bf[4][2];
#pragma unroll
            for (int mi = 0; mi < 4; mi++) {
                int row = wm + mi * 16 + (lane & 15);
                int colb = ks * 32 + ((lane >> 4) << 4);
                ldmat_x4(af[mi][0], af[mi][1], af[mi][2], af[mi][3],
                         sA + sw128(row * 128 + colb));
            }
#pragma unroll
            for (int nj = 0; nj < 2; nj++) {
                int nrow = wn + nj * 16 + (lane & 7) + ((lane >> 4) << 3);
                int kcolb = ks * 32 + (((lane >> 3) & 1) << 4);
                uint32_t r0, r1, r2, r3;
                ldmat_x4(r0, r1, r2, r3, sB + sw128(nrow * 128 + kcolb));
                bf[nj * 2][0] = r0; bf[nj * 2][1] = r1;
                bf[nj * 2 + 1][0] = r2; bf[nj * 2 + 1][1] = r3;
            }
#pragma unroll
            for (int mi = 0; mi < 4; mi++)
#pragma unroll
                for (int ni = 0; ni < 4; ni++)
                    mma_bf16(acc[mi][ni], af[mi], bf[ni]);
        }
    }

    gemm_epilogue<N, MODE>(acc, bm, bn, wm, wn, lane, bias, res, outf, outb);
}

#define GEMM_SMEM_DYN 65536

// ---------------- weight transpose + fp32->bf16 ----------------
__global__ void transpose_bf16(const float* __restrict__ src, __nv_bfloat16* __restrict__ dst,
                               int Rs, int Cs) {
    __shared__ float t[32][33];
    int c = blockIdx.x * 32 + threadIdx.x;
    int r = blockIdx.y * 32 + threadIdx.y;
    t[threadIdx.y][threadIdx.x] = src[(size_t)r * Cs + c];
    __syncthreads();
    int oc = blockIdx.y * 32 + threadIdx.x;
    int orr = blockIdx.x * 32 + threadIdx.y;
    dst[(size_t)orr * Rs + oc] = __float2bfloat16(t[threadIdx.x][threadIdx.y]);
}

// ---------------- u-vectors ----------------
__global__ void attn_u_kernel(const float* __restrict__ W_gat,
                              const float* __restrict__ att_src,
                              const float* __restrict__ att_dst) {
    int c = blockIdx.x * 128 + threadIdx.x;
    if (c >= Cn) return;
    const float* wr = W_gat + (size_t)c * Cn;
#pragma unroll
    for (int h = 0; h < Hn; h++) {
        float s1 = 0.f, s2 = 0.f;
#pragma unroll
        for (int f = 0; f < Fn; f++) {
            float wv = wr[h * Fn + f];
            s1 += wv * att_src[h * Fn + f];
            s2 += wv * att_dst[h * Fn + f];
        }
        g_usrc[h * Cn + c] = s1;
        g_udst[h * Cn + c] = s2;
    }
}

// ---------------- fused LN1 + attention coefficients ----------------
__global__ void ln1_attn_kernel(const float* __restrict__ x, const float* __restrict__ g,
                                const float* __restrict__ b, __nv_bfloat16* __restrict__ out) {
    int row = blockIdx.x;
    int tid = threadIdx.x; // 128
    const float* xr = x + (size_t)row * Cn;
    float v0 = xr[tid], v1 = xr[tid + 128], v2 = xr[tid + 256];
    float s  = v0 + v1 + v2;
    float s2 = v0 * v0 + v1 * v1 + v2 * v2;
#pragma unroll
    for (int o = 16; o; o >>= 1) {
        s  += __shfl_xor_sync(0xffffffffu, s,  o);
        s2 += __shfl_xor_sync(0xffffffffu, s2, o);
    }
    __shared__ float ps[4], ps2[4];
    __shared__ float pdot[12][4];
    if ((tid & 31) == 0) { ps[tid >> 5] = s; ps2[tid >> 5] = s2; }
    __syncthreads();
    s  = ps[0] + ps[1] + ps[2] + ps[3];
    s2 = ps2[0] + ps2[1] + ps2[2] + ps2[3];
    float mu  = s * (1.0f / Cn);
    float var = s2 * (1.0f / Cn) - mu * mu;
    float inv = rsqrtf(var + LN_EPS);
    float xn0 = (v0 - mu) * inv * g[tid]       + b[tid];
    float xn1 = (v1 - mu) * inv * g[tid + 128] + b[tid + 128];
    float xn2 = (v2 - mu) * inv * g[tid + 256] + b[tid + 256];
    __nv_bfloat16* orow = out + (size_t)row * Cn;
    orow[tid]       = __float2bfloat16(xn0);
    orow[tid + 128] = __float2bfloat16(xn1);
    orow[tid + 256] = __float2bfloat16(xn2);

    float d[12];
#pragma unroll
    for (int h = 0; h < Hn; h++) {
        const float* u1 = g_usrc + h * Cn;
        const float* u2 = g_udst + h * Cn;
        d[h]     = xn0 * u1[tid] + xn1 * u1[tid + 128] + xn2 * u1[tid + 256];
        d[h + 6] = xn0 * u2[tid] + xn1 * u2[tid + 128] + xn2 * u2[tid + 256];
    }
#pragma unroll
    for (int j = 0; j < 12; j++) {
        float v = d[j];
#pragma unroll
        for (int o = 16; o; o >>= 1) v += __shfl_xor_sync(0xffffffffu, v, o);
        if ((tid & 31) == 0) pdot[j][tid >> 5] = v;
    }
    __syncthreads();
    if (tid < 12) {
        float v = pdot[tid][0] + pdot[tid][1] + pdot[tid][2] + pdot[tid][3];
        if (tid < 6) g_asrc[(size_t)row * Hn + tid] = v;
        else         g_adst[(size_t)row * Hn + (tid - 6)] = v;
    }
}

// ---------------- CSR build ----------------
__global__ void zero_cnt_kernel() {
    int i = blockIdx.x * blockDim.x + threadIdx.x;
    if (i <= Tn) g_cnt[i] = 0;
}
__global__ void hist_kernel(const int* __restrict__ edge_dst) {
    int e = blockIdx.x * blockDim.x + threadIdx.x;
    if (e >= NEDGE) return;
    int d = (e < En) ? edge_dst[e] : (e - En);
    atomicAdd(&g_cnt[d], 1);
}
__global__ void scan_kernel() {
    __shared__ int sm[1024];
    int t = threadIdx.x;
    int c0 = g_cnt[4 * t + 0], c1 = g_cnt[4 * t + 1];
    int c2 = g_cnt[4 * t + 2], c3 = g_cnt[4 * t + 3];
    int val = c0 + c1 + c2 + c3;
    sm[t] = val;
    __syncthreads();
    for (int d = 1; d < 1024; d <<= 1) {
        int v = (t >= d) ? sm[t - d] : 0;
        __syncthreads();
        if (t >= d) sm[t] += v;
        __syncthreads();
    }
    int base = sm[t] - val;
    g_off[4 * t + 0] = base;                g_cur[4 * t + 0] = base;
    g_off[4 * t + 1] = base + c0;           g_cur[4 * t + 1] = base + c0;
    g_off[4 * t + 2] = base + c0 + c1;      g_cur[4 * t + 2] = base + c0 + c1;
    g_off[4 * t + 3] = base + c0 + c1 + c2; g_cur[4 * t + 3] = base + c0 + c1 + c2;
    if (t == 1023) g_off[Tn] = sm[1023];
}
__global__ void scatter_kernel(const int* __restrict__ edge_src,
                               const int* __restrict__ edge_dst) {
    int e = blockIdx.x * blockDim.x + threadIdx.x;
    if (e >= NEDGE) return;
    int s, d;
    if (e < En) { s = edge_src[e]; d = edge_dst[e]; }
    else        { s = e - En;      d = e - En; }
    int p = atomicAdd(&g_cur[d], 1);
    g_csrc[p] = s;
}

// ---------------- fused GAT aggregation + LN2 ----------------
__global__ __launch_bounds__(192) void gat_ln2_kernel(
    const __nv_bfloat16* __restrict__ Hb,
    const float* __restrict__ asrc,
    const float* __restrict__ adst,
    const float* __restrict__ x,
    const float* __restrict__ bgat,
    const float* __restrict__ ln2g,
    const float* __restrict__ ln2b,
    float* __restrict__ y1,
    __nv_bfloat16* __restrict__ xnb)
{
    __shared__ float y1s[Cn];
    __shared__ float pls[6], pls2[6];

    int n = blockIdx.x;          // b*T + t
    int t = n % Tn;
    int b = n / Tn;
    int wid = threadIdx.x >> 5;  // head
    int lane = threadIdx.x & 31;
    int h = wid;
    int quarter = lane >> 3;
    int sub = lane & 7;
    int beg = g_off[t], end = g_off[t + 1];
    int nb = b * Tn;
    float a_d = adst[(size_t)n * Hn + h];

    float den = 0.f;
    float acc[8] = {};

    for (int e = beg + quarter; e < end; e += 4) {
        int s = g_csrc[e];
        int row = nb + s;
        float al = asrc[(size_t)row * Hn + h] + a_d;
        al = (al >= 0.f) ? al : NEG_SLOPE * al;
        float wgt = __expf(al);
        den += wgt;
        uint4 raw = *(const uint4*)(Hb + (size_t)row * Cn + h * Fn + sub * 8);
        __nv_bfloat162 p0 = *(__nv_bfloat162*)&raw.x;
        __nv_bfloat162 p1 = *(__nv_bfloat162*)&raw.y;
        __nv_bfloat162 p2 = *(__nv_bfloat162*)&raw.z;
        __nv_bfloat162 p3 = *(__nv_bfloat162*)&raw.w;
        acc[0] += wgt * __bfloat162float(p0.x);
        acc[1] += wgt * __bfloat162float(p0.y);
        acc[2] += wgt * __bfloat162float(p1.x);
        acc[3] += wgt * __bfloat162float(p1.y);
        acc[4] += wgt * __bfloat162float(p2.x);
        acc[5] += wgt * __bfloat162float(p2.y);
        acc[6] += wgt * __bfloat162float(p3.x);
        acc[7] += wgt * __bfloat162float(p3.y);
    }
#pragma unroll
    for (int o = 8; o <= 16; o <<= 1) {
        den += __shfl_xor_sync(0xffffffffu, den, o);
#pragma unroll
        for (int j = 0; j < 8; j++)
            acc[j] += __shfl_xor_sync(0xffffffffu, acc[j], o);
    }

    if (quarter == 0) {
        float inv = 1.f / den;
        int c = h * Fn + sub * 8;
        size_t o = (size_t)n * Cn + c;
        float4 x0 = *(const float4*)(x + o);
        float4 x1 = *(const float4*)(x + o + 4);
        float4 bg0 = *(const float4*)(bgat + c);
        float4 bg1 = *(const float4*)(bgat + c + 4);
        float4 r0, r1;
        r0.x = x0.x + acc[0] * inv + bg0.x;
        r0.y = x0.y + acc[1] * inv + bg0.y;
        r0.z = x0.z + acc[2] * inv + bg0.z;
        r0.w = x0.w + acc[3] * inv + bg0.w;
        r1.x = x1.x + acc[4] * inv + bg1.x;
        r1.y = x1.y + acc[5] * inv + bg1.y;
        r1.z = x1.z + acc[6] * inv + bg1.z;
        r1.w = x1.w + acc[7] * inv + bg1.w;
        *(float4*)(y1 + o) = r0;
        *(float4*)(y1 + o + 4) = r1;
        *(float4*)(&y1s[c]) = r0;
        *(float4*)(&y1s[c + 4]) = r1;
    }
    __syncthreads();

    int tid = threadIdx.x;
    float u0 = y1s[tid], u1 = y1s[tid + 192];
    float s  = u0 + u1;
    float s2 = u0 * u0 + u1 * u1;
#pragma unroll
    for (int o = 16; o; o >>= 1) {
        s  += __shfl_xor_sync(0xffffffffu, s,  o);
        s2 += __shfl_xor_sync(0xffffffffu, s2, o);
    }
    if (lane == 0) { pls[wid] = s; pls2[wid] = s2; }
    __syncthreads();
    s  = pls[0] + pls[1] + pls[2] + pls[3] + pls[4] + pls[5];
    s2 = pls2[0] + pls2[1] + pls2[2] + pls2[3] + pls2[4] + pls2[5];
    float mu  = s * (1.0f / Cn);
    float var = s2 * (1.0f / Cn) - mu * mu;
    float inv = rsqrtf(var + LN_EPS);
    __nv_bfloat16* orow = xnb + (size_t)n * Cn;
    orow[tid]       = __float2bfloat16((u0 - mu) * inv * ln2g[tid]       + ln2b[tid]);
    orow[tid + 192] = __float2bfloat16((u1 - mu) * inv * ln2g[tid + 192] + ln2b[tid + 192]);
}

// ---------------- launch ----------------
extern "C" void kernel_launch(void* const* d_in, const int* in_sizes, int n_in,
                              void* d_out, int out_size) {
    const float* x        = (const float*)d_in[0];
    const int*   edge     = (const int*)d_in[1];
    const float* W_gat    = (const float*)d_in[2];
    const float* att_src  = (const float*)d_in[3];
    const float* att_dst  = (const float*)d_in[4];
    const float* b_gat    = (const float*)d_in[5];
    const float* ln1_g    = (const float*)d_in[6];
    const float* ln1_b    = (const float*)d_in[7];
    const float* ln2_g    = (const float*)d_in[8];
    const float* ln2_b    = (const float*)d_in[9];
    const float* W1       = (const float*)d_in[10];
    const float* b1       = (const float*)d_in[11];
    const float* W2       = (const float*)d_in[12];
    const float* b2       = (const float*)d_in[13];
    float* out = (float*)d_out;

    const int* edge_src = edge;
    const int* edge_dst = edge + En;

    __nv_bfloat16 *xnb, *hb, *z, *w1t, *w2t, *wgt;
    float *asrc, *adst, *y1;
    cudaGetSymbolAddress((void**)&xnb,  g_xnb);
    cudaGetSymbolAddress((void**)&hb,   g_hb);
    cudaGetSymbolAddress((void**)&asrc, g_asrc);
    cudaGetSymbolAddress((void**)&adst, g_adst);
    cudaGetSymbolAddress((void**)&y1,   g_y1);
    cudaGetSymbolAddress((void**)&z,    g_z);
    cudaGetSymbolAddress((void**)&w1t,  g_w1t);
    cudaGetSymbolAddress((void**)&w2t,  g_w2t);
    cudaGetSymbolAddress((void**)&wgt,  g_wgt);

    // opt-in to 64KB dynamic smem for the BK=64 FFN2 GEMM (idempotent)
    cudaFuncSetAttribute(gemm_mma64<Cn, DFF, 2>,
                         cudaFuncAttributeMaxDynamicSharedMemorySize, GEMM_SMEM_DYN);

    // (1) attn_u, (2) fused LN1+attn, (3) W_gat^T, (4) GAT GEMM  <- profiled slot
    attn_u_kernel<<<(Cn + 127) / 128, 128>>>(W_gat, att_src, att_dst);
    ln1_attn_kernel<<<BT, 128>>>(x, ln1_g, ln1_b, xnb);
    transpose_bf16<<<dim3(Cn / 32, Cn / 32), dim3(32, 32)>>>(W_gat, wgt, Cn, Cn);
    gemm_mma3<Cn, Cn, 3><<<dim3(Cn / 128, BT / 128), 256>>>(
        xnb, wgt, nullptr, nullptr, nullptr, hb);

    // CSR build (graph shared across batch)
    zero_cnt_kernel<<<(Tn + 256) / 256, 256>>>();
    hist_kernel<<<(NEDGE + 255) / 256, 256>>>(edge_dst);
    scan_kernel<<<1, 1024>>>();
    scatter_kernel<<<(NEDGE + 255) / 256, 256>>>(edge_src, edge_dst);

    // remaining weight transposes
    transpose_bf16<<<dim3(DFF / 32, Cn / 32), dim3(32, 32)>>>(W1, w1t, Cn, DFF);
    transpose_bf16<<<dim3(Cn / 32, DFF / 32), dim3(32, 32)>>>(W2, w2t, DFF, Cn);

    // fused aggregation + LN2: writes y1 and xnb
    gat_ln2_kernel<<<BT, 192>>>(hb, asrc, adst, x, b_gat, ln2_g, ln2_b, y1, xnb);

    // FFN1: Z = relu(xn @ W1 + b1)  (bf16 out, K=384 -> 3-stage BK=32)
    gemm_mma3<DFF, Cn, 1><<<dim3(DFF / 128, BT / 128), 256>>>(
        xnb, w1t, b1, nullptr, nullptr, z);
    // FFN2: out = Z @ W2 + b2 + y1 (fp32 out, K=1536 -> 2-stage BK=64)
    gemm_mma64<Cn, DFF, 2><<<dim3(Cn / 128, BT / 128), 256, GEMM_SMEM_DYN>>>(
        z, w2t, b2, y1, out, nullptr);
}